// round 3
// baseline (speedup 1.0000x reference)
#include <cuda_runtime.h>
#include <math.h>
#include <stdint.h>

#define DIMC 384
#define NH 6
#define HD 64
#define MLPD 1536
#define BATCH 8
#define SEQ 1024
#define M_TOT (BATCH*SEQ)
#define LN_EPS 1e-5f

__device__ float g_h[M_TOT * DIMC];
__device__ float g_qkv[M_TOT * 3 * DIMC];
__device__ float g_ao[M_TOT * DIMC];
__device__ float g_x1[M_TOT * DIMC];
__device__ float g_m[M_TOT * MLPD];

__device__ __forceinline__ float tf32r(float x) {
    float y; asm("cvt.rna.tf32.f32 %0, %1;" : "=f"(y) : "f"(x)); return y;
}

__device__ __forceinline__ void mma_tf32(float c[4], uint32_t a0, uint32_t a1,
                                         uint32_t a2, uint32_t a3,
                                         uint32_t b0, uint32_t b1) {
    asm volatile(
        "mma.sync.aligned.m16n8k8.row.col.f32.tf32.tf32.f32 "
        "{%0,%1,%2,%3},{%4,%5,%6,%7},{%8,%9},{%0,%1,%2,%3};\n"
        : "+f"(c[0]), "+f"(c[1]), "+f"(c[2]), "+f"(c[3])
        : "r"(a0), "r"(a1), "r"(a2), "r"(a3), "r"(b0), "r"(b1));
}
__device__ __forceinline__ void mma_tf32f(float c[4], float a0, float a1,
                                          float a2, float a3, float b0, float b1) {
    mma_tf32(c, __float_as_uint(a0), __float_as_uint(a1), __float_as_uint(a2),
             __float_as_uint(a3), __float_as_uint(b0), __float_as_uint(b1));
}

// ============================================================
// LayerNorm
// ============================================================
__global__ __launch_bounds__(128)
void ln_kernel(const float* __restrict__ x, const float* __restrict__ w,
               const float* __restrict__ b, float* __restrict__ out) {
    int row = blockIdx.x;
    int tid = threadIdx.x;
    const float* xr = x + (size_t)row * DIMC;
    float v0 = xr[tid], v1 = xr[tid + 128], v2 = xr[tid + 256];

    __shared__ float red[4];
    float s = v0 + v1 + v2;
    #pragma unroll
    for (int o = 16; o > 0; o >>= 1) s += __shfl_down_sync(0xffffffff, s, o);
    if ((tid & 31) == 0) red[tid >> 5] = s;
    __syncthreads();
    float mean = (red[0] + red[1] + red[2] + red[3]) * (1.0f / DIMC);
    __syncthreads();

    float d0 = v0 - mean, d1 = v1 - mean, d2 = v2 - mean;
    float q = d0 * d0 + d1 * d1 + d2 * d2;
    #pragma unroll
    for (int o = 16; o > 0; o >>= 1) q += __shfl_down_sync(0xffffffff, q, o);
    if ((tid & 31) == 0) red[tid >> 5] = q;
    __syncthreads();
    float var = (red[0] + red[1] + red[2] + red[3]) * (1.0f / DIMC);
    float r = rsqrtf(var + LN_EPS);

    float* orow = out + (size_t)row * DIMC;
    orow[tid]       = d0 * r * w[tid]       + b[tid];
    orow[tid + 128] = d1 * r * w[tid + 128] + b[tid + 128];
    orow[tid + 256] = d2 * r * w[tid + 256] + b[tid + 256];
}

// ============================================================
// TF32 TC GEMM: C[M,N] = A[M,K] @ W[N,K]^T (+epilogue)
// 128x128 tile, BK=32, 256 thr, warps 2x4 (64x32).
// smem pair layout: within each 8-k group, element k at pos
//   (k&3)*2 + ((k>>2)&1)  -> (k, k+4) adjacent -> v2 loads.
// ============================================================
#define SKS 34           // smem row stride (floats), BK=32 + pad2
#define GEMM_SMEM (4 * 128 * SKS * 4)   // 2 stages A + 2 stages B

__device__ __forceinline__ void st_pair8(float* dst, float4 lo, float4 hi) {
    ((float2*)dst)[0] = make_float2(tf32r(lo.x), tf32r(hi.x));
    ((float2*)dst)[1] = make_float2(tf32r(lo.y), tf32r(hi.y));
    ((float2*)dst)[2] = make_float2(tf32r(lo.z), tf32r(hi.z));
    ((float2*)dst)[3] = make_float2(tf32r(lo.w), tf32r(hi.w));
}

template <int EPI>
__global__ __launch_bounds__(256, 2)
void gemm_tc(const float* __restrict__ A, const float* __restrict__ W,
             const float* __restrict__ bias, const float* __restrict__ res,
             float* __restrict__ C, int M, int N, int K) {
    extern __shared__ float smem[];
    float* As = smem;                    // [2][128*SKS]
    float* Bs = smem + 2 * 128 * SKS;

    int tid = threadIdx.x;
    int lane = tid & 31, wid = tid >> 5;
    int wm = wid >> 2, wn = wid & 3;
    int j = lane & 3, lr4 = lane >> 2;
    int m0 = blockIdx.y * 128, n0 = blockIdx.x * 128;

    int row = tid >> 1;            // 0..127
    int kh = tid & 1;              // segment bases kh*8, kh*8+16
    const float* Ap = A + (size_t)(m0 + row) * K + kh * 8;
    const float* Wp = W + (size_t)(n0 + row) * K + kh * 8;

    float acc[4][4][4];
    #pragma unroll
    for (int i = 0; i < 4; i++)
        #pragma unroll
        for (int jj = 0; jj < 4; jj++)
            #pragma unroll
            for (int r = 0; r < 4; r++) acc[i][jj][r] = 0.f;

    int T = K / 32;
    float4 al0, ah0, al1, ah1, bl0, bh0, bl1, bh1;
    // prologue load stage 0
    al0 = *(const float4*)(Ap);      ah0 = *(const float4*)(Ap + 4);
    al1 = *(const float4*)(Ap + 16); ah1 = *(const float4*)(Ap + 20);
    bl0 = *(const float4*)(Wp);      bh0 = *(const float4*)(Wp + 4);
    bl1 = *(const float4*)(Wp + 16); bh1 = *(const float4*)(Wp + 20);
    st_pair8(&As[row * SKS + kh * 8],      al0, ah0);
    st_pair8(&As[row * SKS + kh * 8 + 16], al1, ah1);
    st_pair8(&Bs[row * SKS + kh * 8],      bl0, bh0);
    st_pair8(&Bs[row * SKS + kh * 8 + 16], bl1, bh1);
    __syncthreads();

    for (int t = 0; t < T; t++) {
        int s = t & 1;
        float* Ast = As + s * 128 * SKS;
        float* Bst = Bs + s * 128 * SKS;
        if (t + 1 < T) {
            const float* Ap2 = Ap + (t + 1) * 32;
            const float* Wp2 = Wp + (t + 1) * 32;
            al0 = *(const float4*)(Ap2);      ah0 = *(const float4*)(Ap2 + 4);
            al1 = *(const float4*)(Ap2 + 16); ah1 = *(const float4*)(Ap2 + 20);
            bl0 = *(const float4*)(Wp2);      bh0 = *(const float4*)(Wp2 + 4);
            bl1 = *(const float4*)(Wp2 + 16); bh1 = *(const float4*)(Wp2 + 20);
        }
        #pragma unroll
        for (int kk = 0; kk < 32; kk += 8) {
            float2 af0[4], af1[4];
            #pragma unroll
            for (int mi = 0; mi < 4; mi++) {
                int mr = wm * 64 + mi * 16 + lr4;
                af0[mi] = *(const float2*)&Ast[mr * SKS + kk + 2 * j];        // (a0,a2)
                af1[mi] = *(const float2*)&Ast[(mr + 8) * SKS + kk + 2 * j];  // (a1,a3)
            }
            #pragma unroll
            for (int ni = 0; ni < 4; ni++) {
                int nr = wn * 32 + ni * 8 + lr4;
                float2 bf = *(const float2*)&Bst[nr * SKS + kk + 2 * j];      // (b0,b1)
                #pragma unroll
                for (int mi = 0; mi < 4; mi++)
                    mma_tf32f(acc[mi][ni], af0[mi].x, af1[mi].x,
                              af0[mi].y, af1[mi].y, bf.x, bf.y);
            }
        }
        if (t + 1 < T) {
            int s2 = s ^ 1;
            float* Asn = As + s2 * 128 * SKS;
            float* Bsn = Bs + s2 * 128 * SKS;
            st_pair8(&Asn[row * SKS + kh * 8],      al0, ah0);
            st_pair8(&Asn[row * SKS + kh * 8 + 16], al1, ah1);
            st_pair8(&Bsn[row * SKS + kh * 8],      bl0, bh0);
            st_pair8(&Bsn[row * SKS + kh * 8 + 16], bl1, bh1);
        }
        __syncthreads();
    }

    #pragma unroll
    for (int mi = 0; mi < 4; mi++) {
        int r = m0 + wm * 64 + mi * 16 + lr4;
        #pragma unroll
        for (int ni = 0; ni < 4; ni++) {
            int c = n0 + wn * 32 + ni * 8 + 2 * j;
            float v[4] = {acc[mi][ni][0], acc[mi][ni][1], acc[mi][ni][2], acc[mi][ni][3]};
            int rr[2] = {r, r + 8};
            #pragma unroll
            for (int half = 0; half < 2; half++) {
                float x0 = v[half * 2 + 0], x1 = v[half * 2 + 1];
                if (EPI == 1) {
                    x0 += bias[c] + res[(size_t)rr[half] * N + c];
                    x1 += bias[c + 1] + res[(size_t)rr[half] * N + c + 1];
                }
                if (EPI == 2) {
                    x0 += bias[c];
                    x1 += bias[c + 1];
                    x0 = 0.5f * x0 * (1.0f + erff(x0 * 0.70710678118654752f));
                    x1 = 0.5f * x1 * (1.0f + erff(x1 * 0.70710678118654752f));
                }
                *(float2*)(C + (size_t)rr[half] * N + c) = make_float2(x0, x1);
            }
        }
    }
}

// ============================================================
// L2Q attention. 128 thr / 4 warps, Q-tile 64 rows (16/warp).
// Q frags in regs (pre-scaled by 0.125). K: Ks[key][pairpos(d)].
// V: Vt[d][pairpos(key)]. F: per-warp ping-pong smem bounce.
// ============================================================
#define AKS 68     // Ks/Vt row stride
#define FWS 10     // Fw row stride

__global__ __launch_bounds__(128, 5)
void attn_tc(const float* __restrict__ qkv,
             const float* __restrict__ alpha, const float* __restrict__ beta,
             const float* __restrict__ gamma, float* __restrict__ ao) {
    __shared__ float Ks[64 * AKS];
    __shared__ float Vt[64 * AKS];
    __shared__ float Fw[4][2][16 * FWS];

    int tid = threadIdx.x, lane = tid & 31, wid = tid >> 5;
    int j = lane & 3, lr4 = lane >> 2;
    int bh = blockIdx.y;
    int b = bh / NH, h = bh % NH;
    int r0 = blockIdx.x * 64;
    float al = alpha[h], be = beta[h], ga = gamma[h];

    const float* qbase = qkv + (size_t)b * SEQ * (3 * DIMC) + h * HD;
    const float* kbase = qbase + DIMC;
    const float* vbase = qbase + 2 * DIMC;

    // Q fragments in registers (scale folded: 0.125 is exact)
    float qf[8][4];
    {
        const float* qlo = qbase + (size_t)(r0 + wid * 16 + lr4) * (3 * DIMC);
        const float* qhi = qlo + 8 * (3 * DIMC);
        #pragma unroll
        for (int dk = 0; dk < 8; dk++) {
            qf[dk][0] = tf32r(qlo[dk * 8 + j] * 0.125f);
            qf[dk][1] = tf32r(qhi[dk * 8 + j] * 0.125f);
            qf[dk][2] = tf32r(qlo[dk * 8 + j + 4] * 0.125f);
            qf[dk][3] = tf32r(qhi[dk * 8 + j + 4] * 0.125f);
        }
    }

    float oacc[8][4];
    #pragma unroll
    for (int i = 0; i < 8; i++)
        #pragma unroll
        for (int r = 0; r < 4; r++) oacc[i][r] = 0.f;
    float den0 = 0.f, den1 = 0.f;

    int lrow = tid >> 1;           // 0..63 (key row for loads)
    int dh = tid & 1;
    int kx = ((lrow >> 3) << 3) + ((lrow & 3) * 2) + ((lrow >> 2) & 1);  // pairpos(key)

    for (int t = 0; t < SEQ / 64; t++) {
        int kk0 = t * 64;
        __syncthreads();
        // K tile: paired over d
        {
            const float* kr = kbase + (size_t)(kk0 + lrow) * (3 * DIMC);
            #pragma unroll
            for (int sgi = 0; sgi < 4; sgi++) {
                int base = dh * 8 + sgi * 16;
                float4 lo = *(const float4*)(kr + base);
                float4 hi = *(const float4*)(kr + base + 4);
                st_pair8(&Ks[lrow * AKS + base], lo, hi);
            }
        }
        // V tile: transposed, paired over key
        {
            const float* vr = vbase + (size_t)(kk0 + lrow) * (3 * DIMC) + dh * 32;
            #pragma unroll
            for (int sgi = 0; sgi < 8; sgi++) {
                float4 v = *(const float4*)(vr + sgi * 4);
                int d = dh * 32 + sgi * 4;
                Vt[(d + 0) * AKS + kx] = tf32r(v.x);
                Vt[(d + 1) * AKS + kx] = tf32r(v.y);
                Vt[(d + 2) * AKS + kx] = tf32r(v.z);
                Vt[(d + 3) * AKS + kx] = tf32r(v.w);
            }
        }
        __syncthreads();

        #pragma unroll
        for (int ni = 0; ni < 8; ni++) {
            int bk = ni * 8;
            // S chunk: 16 q-rows x 8 keys
            float sa[4] = {0.f, 0.f, 0.f, 0.f};
            #pragma unroll
            for (int dk = 0; dk < 8; dk++) {
                float2 bf = *(const float2*)&Ks[(bk + lr4) * AKS + dk * 8 + 2 * j];
                mma_tf32f(sa, qf[dk][0], qf[dk][1], qf[dk][2], qf[dk][3], bf.x, bf.y);
            }
            // transform: f = relu(al*s^2 + be*s + ga)
            float f0 = fmaxf(fmaf(al * sa[0], sa[0], fmaf(be, sa[0], ga)), 0.f);
            float f1 = fmaxf(fmaf(al * sa[1], sa[1], fmaf(be, sa[1], ga)), 0.f);
            float f2 = fmaxf(fmaf(al * sa[2], sa[2], fmaf(be, sa[2], ga)), 0.f);
            float f3 = fmaxf(fmaf(al * sa[3], sa[3], fmaf(be, sa[3], ga)), 0.f);
            den0 += f0 + f1;
            den1 += f2 + f3;
            // bounce through per-warp smem to reshape acc->A-frag
            float* fw = Fw[wid][ni & 1];
            int pe = (2 * j) & 3, po = (2 * j + 1) & 3;     // pos8 of cols 2j, 2j+1
            int ppe = pe * 2 + ((2 * j) >> 2);
            int ppo = po * 2 + ((2 * j + 1) >> 2);
            fw[lr4 * FWS + ppe] = tf32r(f0);
            fw[lr4 * FWS + ppo] = tf32r(f1);
            fw[(lr4 + 8) * FWS + ppe] = tf32r(f2);
            fw[(lr4 + 8) * FWS + ppo] = tf32r(f3);
            __syncwarp();
            float2 falo = *(const float2*)&fw[lr4 * FWS + 2 * j];        // (a0,a2)
            float2 fahi = *(const float2*)&fw[(lr4 + 8) * FWS + 2 * j];  // (a1,a3)
            // O += F_chunk * V_chunk
            #pragma unroll
            for (int di = 0; di < 8; di++) {
                float2 bf = *(const float2*)&Vt[(di * 8 + lr4) * AKS + bk + 2 * j];
                mma_tf32f(oacc[di], falo.x, fahi.x, falo.y, fahi.y, bf.x, bf.y);
            }
        }
    }

    den0 += __shfl_xor_sync(0xffffffff, den0, 1);
    den0 += __shfl_xor_sync(0xffffffff, den0, 2);
    den1 += __shfl_xor_sync(0xffffffff, den1, 1);
    den1 += __shfl_xor_sync(0xffffffff, den1, 2);
    float di0 = 1.0f / (den0 + 1e-6f);
    float di1 = 1.0f / (den1 + 1e-6f);

    float* olo = ao + (size_t)(b * SEQ + r0 + wid * 16 + lr4) * DIMC + h * HD;
    float* ohi = olo + 8 * DIMC;
    #pragma unroll
    for (int di = 0; di < 8; di++) {
        int c = di * 8 + 2 * j;
        *(float2*)(olo + c) = make_float2(oacc[di][0] * di0, oacc[di][1] * di0);
        *(float2*)(ohi + c) = make_float2(oacc[di][2] * di1, oacc[di][3] * di1);
    }
}

// ============================================================
// launch
// ============================================================
extern "C" void kernel_launch(void* const* d_in, const int* in_sizes, int n_in,
                              void* d_out, int out_size) {
    const float* x      = (const float*)d_in[0];
    const float* qkv_w  = (const float*)d_in[1];
    const float* proj_w = (const float*)d_in[2];
    const float* proj_b = (const float*)d_in[3];
    const float* alpha  = (const float*)d_in[4];
    const float* beta   = (const float*)d_in[5];
    const float* gamma  = (const float*)d_in[6];
    const float* ln1_w  = (const float*)d_in[7];
    const float* ln1_b  = (const float*)d_in[8];
    const float* ln2_w  = (const float*)d_in[9];
    const float* ln2_b  = (const float*)d_in[10];
    const float* w1     = (const float*)d_in[11];
    const float* b1     = (const float*)d_in[12];
    const float* w2     = (const float*)d_in[13];
    const float* b2     = (const float*)d_in[14];
    float* out = (float*)d_out;

    float *h, *qkv, *ao, *x1, *m;
    cudaGetSymbolAddress((void**)&h,   g_h);
    cudaGetSymbolAddress((void**)&qkv, g_qkv);
    cudaGetSymbolAddress((void**)&ao,  g_ao);
    cudaGetSymbolAddress((void**)&x1,  g_x1);
    cudaGetSymbolAddress((void**)&m,   g_m);

    static int configured = 0;
    if (!configured) {
        cudaFuncSetAttribute(gemm_tc<0>, cudaFuncAttributeMaxDynamicSharedMemorySize, GEMM_SMEM);
        cudaFuncSetAttribute(gemm_tc<1>, cudaFuncAttributeMaxDynamicSharedMemorySize, GEMM_SMEM);
        cudaFuncSetAttribute(gemm_tc<2>, cudaFuncAttributeMaxDynamicSharedMemorySize, GEMM_SMEM);
        configured = 1;
    }

    ln_kernel<<<M_TOT, 128>>>(x, ln1_w, ln1_b, h);
    gemm_tc<0><<<dim3(3 * DIMC / 128, M_TOT / 128), 256, GEMM_SMEM>>>(
        h, qkv_w, nullptr, nullptr, qkv, M_TOT, 3 * DIMC, DIMC);
    attn_tc<<<dim3(SEQ / 64, BATCH * NH), 128>>>(qkv, alpha, beta, gamma, ao);
    gemm_tc<1><<<dim3(DIMC / 128, M_TOT / 128), 256, GEMM_SMEM>>>(
        ao, proj_w, proj_b, x, x1, M_TOT, DIMC, DIMC);
    ln_kernel<<<M_TOT, 128>>>(x1, ln2_w, ln2_b, h);
    gemm_tc<2><<<dim3(MLPD / 128, M_TOT / 128), 256, GEMM_SMEM>>>(
        h, w1, b1, nullptr, m, M_TOT, MLPD, DIMC);
    gemm_tc<1><<<dim3(DIMC / 128, M_TOT / 128), 256, GEMM_SMEM>>>(
        m, w2, b2, x1, out, M_TOT, DIMC, MLPD);
}

// round 4
// speedup vs baseline: 1.6980x; 1.6980x over previous
#include <cuda_runtime.h>
#include <math.h>
#include <stdint.h>

#define DIMC 384
#define NH 6
#define HD 64
#define MLPD 1536
#define BATCH 8
#define SEQ 1024
#define M_TOT (BATCH*SEQ)
#define LN_EPS 1e-5f

// sizes of the four weight matrices
#define NW_QKV (3*DIMC*DIMC)     // 442368
#define NW_PROJ (DIMC*DIMC)      // 147456
#define NW_1 (MLPD*DIMC)         // 589824
#define NW_2 (DIMC*MLPD)         // 589824

__device__ float g_h[M_TOT * DIMC];
__device__ float g_qkv[M_TOT * 3 * DIMC];
__device__ float g_ao[M_TOT * DIMC];
__device__ float g_x1[M_TOT * DIMC];
__device__ float g_m[M_TOT * MLPD];
__device__ float g_wq[NW_QKV];
__device__ float g_wp[NW_PROJ];
__device__ float g_w1[NW_1];
__device__ float g_w2[NW_2];

__device__ __forceinline__ float tf32r(float x) {
    float y; asm("cvt.rna.tf32.f32 %0, %1;" : "=f"(y) : "f"(x)); return y;
}

__device__ __forceinline__ void mma_tf32f(float c[4], float a0, float a1,
                                          float a2, float a3, float b0, float b1) {
    asm volatile(
        "mma.sync.aligned.m16n8k8.row.col.f32.tf32.tf32.f32 "
        "{%0,%1,%2,%3},{%4,%5,%6,%7},{%8,%9},{%0,%1,%2,%3};\n"
        : "+f"(c[0]), "+f"(c[1]), "+f"(c[2]), "+f"(c[3])
        : "r"(__float_as_uint(a0)), "r"(__float_as_uint(a1)),
          "r"(__float_as_uint(a2)), "r"(__float_as_uint(a3)),
          "r"(__float_as_uint(b0)), "r"(__float_as_uint(b1)));
}

__device__ __forceinline__ void cpa16(uint32_t s, const void* g) {
    asm volatile("cp.async.cg.shared.global [%0], [%1], 16;" :: "r"(s), "l"(g));
}

// ============================================================
// one-shot weight rounding to tf32
// ============================================================
__global__ __launch_bounds__(256)
void round_w(const float* __restrict__ a, float* __restrict__ oa,
             const float* __restrict__ b, float* __restrict__ ob,
             const float* __restrict__ c, float* __restrict__ oc,
             const float* __restrict__ d, float* __restrict__ od) {
    int i = blockIdx.x * 256 + threadIdx.x;
    if (i < NW_QKV)  oa[i] = tf32r(a[i]);
    if (i < NW_PROJ) ob[i] = tf32r(b[i]);
    if (i < NW_1) { oc[i] = tf32r(c[i]); od[i] = tf32r(d[i]); }
}

// ============================================================
// LayerNorm (outputs tf32-rounded; they only feed GEMM A operands)
// ============================================================
__global__ __launch_bounds__(128)
void ln_kernel(const float* __restrict__ x, const float* __restrict__ w,
               const float* __restrict__ b, float* __restrict__ out) {
    int row = blockIdx.x;
    int tid = threadIdx.x;
    const float* xr = x + (size_t)row * DIMC;
    float v0 = xr[tid], v1 = xr[tid + 128], v2 = xr[tid + 256];

    __shared__ float red[4];
    float s = v0 + v1 + v2;
    #pragma unroll
    for (int o = 16; o > 0; o >>= 1) s += __shfl_down_sync(0xffffffff, s, o);
    if ((tid & 31) == 0) red[tid >> 5] = s;
    __syncthreads();
    float mean = (red[0] + red[1] + red[2] + red[3]) * (1.0f / DIMC);
    __syncthreads();

    float d0 = v0 - mean, d1 = v1 - mean, d2 = v2 - mean;
    float q = d0 * d0 + d1 * d1 + d2 * d2;
    #pragma unroll
    for (int o = 16; o > 0; o >>= 1) q += __shfl_down_sync(0xffffffff, q, o);
    if ((tid & 31) == 0) red[tid >> 5] = q;
    __syncthreads();
    float var = (red[0] + red[1] + red[2] + red[3]) * (1.0f / DIMC);
    float r = rsqrtf(var + LN_EPS);

    float* orow = out + (size_t)row * DIMC;
    orow[tid]       = tf32r(d0 * r * w[tid]       + b[tid]);
    orow[tid + 128] = tf32r(d1 * r * w[tid + 128] + b[tid + 128]);
    orow[tid + 256] = tf32r(d2 * r * w[tid + 256] + b[tid + 256]);
}

// ============================================================
// TF32 TC GEMM: C[M,N] = A[M,K] @ W[N,K]^T (+epilogue)
// A/W already tf32-rounded in gmem -> raw cp.async staging.
// 128x128 tile, BK=16, 3-stage cp.async pipeline, 256 thr,
// warps 2x4 (warp tile 64x32), smem stride 20 (conflict-free).
// EPI 0: round(tf32) out  EPI 1: +bias+res (fp32 out)
// EPI 2: +bias, exact GELU, round(tf32) out
// ============================================================
#define AST 20
#define SLOT (128*AST)
#define GEMM_SMEM (6 * SLOT * 4)     // 3 stages x (A+B) = 61440 B

template <int EPI>
__global__ __launch_bounds__(256, 2)
void gemm_tc(const float* __restrict__ A, const float* __restrict__ W,
             const float* __restrict__ bias, const float* __restrict__ res,
             float* __restrict__ C, int M, int N, int K) {
    extern __shared__ float smem[];
    float* As = smem;
    float* Bs = smem + 3 * SLOT;
    uint32_t As_u = (uint32_t)__cvta_generic_to_shared(As);
    uint32_t Bs_u = (uint32_t)__cvta_generic_to_shared(Bs);

    int tid = threadIdx.x;
    int lane = tid & 31, wid = tid >> 5;
    int wm = wid >> 2, wn = wid & 3;
    int j = lane & 3, lr4 = lane >> 2;
    int m0 = blockIdx.y * 128, n0 = blockIdx.x * 128;

    int row = tid >> 1;
    int kq0 = (tid & 1) * 2;            // 16B chunk pair {0,1} or {2,3}
    const float* Ag = A + (size_t)(m0 + row) * K + kq0 * 4;
    const float* Wg = W + (size_t)(n0 + row) * K + kq0 * 4;
    uint32_t sa_off = (row * AST + kq0 * 4) * 4;

    float acc[4][4][4] = {};
    int T = K / 16;

    #pragma unroll
    for (int s = 0; s < 2; s++) {
        uint32_t ab = As_u + s * SLOT * 4 + sa_off;
        uint32_t bb = Bs_u + s * SLOT * 4 + sa_off;
        cpa16(ab, Ag + s * 16);      cpa16(ab + 16, Ag + s * 16 + 4);
        cpa16(bb, Wg + s * 16);      cpa16(bb + 16, Wg + s * 16 + 4);
        asm volatile("cp.async.commit_group;");
    }

    for (int t = 0; t < T; t++) {
        if (t < T - 1) asm volatile("cp.async.wait_group 1;");
        else           asm volatile("cp.async.wait_group 0;");
        __syncthreads();
        if (t + 2 < T) {
            int sl = (t + 2) % 3;
            uint32_t ab = As_u + sl * SLOT * 4 + sa_off;
            uint32_t bb = Bs_u + sl * SLOT * 4 + sa_off;
            const float* Ap2 = Ag + (t + 2) * 16;
            const float* Wp2 = Wg + (t + 2) * 16;
            cpa16(ab, Ap2);      cpa16(ab + 16, Ap2 + 4);
            cpa16(bb, Wp2);      cpa16(bb + 16, Wp2 + 4);
            asm volatile("cp.async.commit_group;");
        }
        const float* Ast = As + (t % 3) * SLOT;
        const float* Bst = Bs + (t % 3) * SLOT;
        #pragma unroll
        for (int kk = 0; kk < 16; kk += 8) {
            float af[4][4];
            #pragma unroll
            for (int mi = 0; mi < 4; mi++) {
                int mr = wm * 64 + mi * 16 + lr4;
                af[mi][0] = Ast[mr * AST + kk + j];
                af[mi][1] = Ast[(mr + 8) * AST + kk + j];
                af[mi][2] = Ast[mr * AST + kk + j + 4];
                af[mi][3] = Ast[(mr + 8) * AST + kk + j + 4];
            }
            #pragma unroll
            for (int ni = 0; ni < 4; ni++) {
                int nr = wn * 32 + ni * 8 + lr4;
                float b0 = Bst[nr * AST + kk + j];
                float b1 = Bst[nr * AST + kk + j + 4];
                #pragma unroll
                for (int mi = 0; mi < 4; mi++)
                    mma_tf32f(acc[mi][ni], af[mi][0], af[mi][1],
                              af[mi][2], af[mi][3], b0, b1);
            }
        }
    }

    #pragma unroll
    for (int mi = 0; mi < 4; mi++) {
        int r = m0 + wm * 64 + mi * 16 + lr4;
        #pragma unroll
        for (int ni = 0; ni < 4; ni++) {
            int c = n0 + wn * 32 + ni * 8 + 2 * j;
            float v[4] = {acc[mi][ni][0], acc[mi][ni][1], acc[mi][ni][2], acc[mi][ni][3]};
            int rr[2] = {r, r + 8};
            #pragma unroll
            for (int half = 0; half < 2; half++) {
                float x0 = v[half * 2 + 0], x1 = v[half * 2 + 1];
                if (EPI == 0) { x0 = tf32r(x0); x1 = tf32r(x1); }
                if (EPI == 1) {
                    x0 += bias[c] + res[(size_t)rr[half] * N + c];
                    x1 += bias[c + 1] + res[(size_t)rr[half] * N + c + 1];
                }
                if (EPI == 2) {
                    x0 += bias[c];
                    x1 += bias[c + 1];
                    x0 = tf32r(0.5f * x0 * (1.0f + erff(x0 * 0.70710678118654752f)));
                    x1 = tf32r(0.5f * x1 * (1.0f + erff(x1 * 0.70710678118654752f)));
                }
                *(float2*)(C + (size_t)rr[half] * N + c) = make_float2(x0, x1);
            }
        }
    }
}

// ============================================================
// L2Q attention (R2 structure). 128 thr / 4 warps, 64-row Q tile.
// Q fragments in registers; K/V tiles via cp.async; F overwrites
// the K smem buffer between barriers. ao written tf32-rounded.
// ============================================================
#define AKS 68

__global__ __launch_bounds__(128, 4)
void attn_tc(const float* __restrict__ qkv,
             const float* __restrict__ alpha, const float* __restrict__ beta,
             const float* __restrict__ gamma, float* __restrict__ ao) {
    __shared__ float KFs[64 * AKS];
    __shared__ float Vs[64 * AKS];
    uint32_t KFs_u = (uint32_t)__cvta_generic_to_shared(KFs);
    uint32_t Vs_u  = (uint32_t)__cvta_generic_to_shared(Vs);

    int tid = threadIdx.x, lane = tid & 31, wid = tid >> 5;
    int j = lane & 3, lr4 = lane >> 2;
    int bh = blockIdx.y;
    int b = bh / NH, h = bh % NH;
    int r0 = blockIdx.x * 64;
    float al = alpha[h], be = beta[h], ga = gamma[h];

    const float* qbase = qkv + (size_t)b * SEQ * (3 * DIMC) + h * HD;
    const float* kbase = qbase + DIMC;
    const float* vbase = qbase + 2 * DIMC;

    int row0 = wid * 16 + lr4;

    // Q fragments in registers (qkv already tf32-rounded)
    float qf[8][4];
    {
        const float* qlo = qbase + (size_t)(r0 + row0) * (3 * DIMC);
        const float* qhi = qlo + 8 * (3 * DIMC);
        #pragma unroll
        for (int dk = 0; dk < 8; dk++) {
            qf[dk][0] = qlo[dk * 8 + j];
            qf[dk][1] = qhi[dk * 8 + j];
            qf[dk][2] = qlo[dk * 8 + j + 4];
            qf[dk][3] = qhi[dk * 8 + j + 4];
        }
    }

    float oacc[8][4];
    #pragma unroll
    for (int i = 0; i < 8; i++)
        #pragma unroll
        for (int r = 0; r < 4; r++) oacc[i][r] = 0.f;
    float den0 = 0.f, den1 = 0.f;

    int lrow = tid >> 1;
    int half = tid & 1;
    uint32_t ks_s = KFs_u + (lrow * AKS + half * 32) * 4;
    uint32_t vs_s = Vs_u  + (lrow * AKS + half * 32) * 4;

    for (int t = 0; t < SEQ / 64; t++) {
        int kk0 = t * 64;
        __syncthreads();    // prior tile reads (K/F/V) complete everywhere
        {
            const float* kr = kbase + (size_t)(kk0 + lrow) * (3 * DIMC) + half * 32;
            const float* vr = vbase + (size_t)(kk0 + lrow) * (3 * DIMC) + half * 32;
            #pragma unroll
            for (int i = 0; i < 8; i++) {
                cpa16(ks_s + i * 16, kr + i * 4);
                cpa16(vs_s + i * 16, vr + i * 4);
            }
            asm volatile("cp.async.commit_group;");
            asm volatile("cp.async.wait_group 0;");
        }
        __syncthreads();

        // S = Q K^T  (per warp: 16 rows x 64 keys)
        float sacc[8][4];
        #pragma unroll
        for (int i = 0; i < 8; i++)
            #pragma unroll
            for (int r = 0; r < 4; r++) sacc[i][r] = 0.f;

        #pragma unroll
        for (int kk = 0; kk < 64; kk += 8) {
            int dk = kk >> 3;
            #pragma unroll
            for (int ni = 0; ni < 8; ni++) {
                int br = ni * 8 + lr4;
                float b0 = KFs[br * AKS + kk + j];
                float b1 = KFs[br * AKS + kk + j + 4];
                mma_tf32f(sacc[ni], qf[dk][0], qf[dk][1], qf[dk][2], qf[dk][3], b0, b1);
            }
        }
        __syncthreads();   // all warps done reading K

        // f = relu(alpha*s^2 + beta*s + gamma); write F into KFs
        #pragma unroll
        for (int ni = 0; ni < 8; ni++) {
            int cc = ni * 8 + 2 * j;
            float s0 = sacc[ni][0] * 0.125f;
            float s1 = sacc[ni][1] * 0.125f;
            float s2 = sacc[ni][2] * 0.125f;
            float s3 = sacc[ni][3] * 0.125f;
            float f0 = fmaxf(fmaf(al * s0, s0, fmaf(be, s0, ga)), 0.f);
            float f1 = fmaxf(fmaf(al * s1, s1, fmaf(be, s1, ga)), 0.f);
            float f2 = fmaxf(fmaf(al * s2, s2, fmaf(be, s2, ga)), 0.f);
            float f3 = fmaxf(fmaf(al * s3, s3, fmaf(be, s3, ga)), 0.f);
            den0 += f0 + f1;
            den1 += f2 + f3;
            KFs[row0 * AKS + cc]           = tf32r(f0);
            KFs[row0 * AKS + cc + 1]       = tf32r(f1);
            KFs[(row0 + 8) * AKS + cc]     = tf32r(f2);
            KFs[(row0 + 8) * AKS + cc + 1] = tf32r(f3);
        }
        __syncthreads();

        // O += F V
        #pragma unroll
        for (int kk = 0; kk < 64; kk += 8) {
            float a0 = KFs[row0 * AKS + kk + j];
            float a1 = KFs[(row0 + 8) * AKS + kk + j];
            float a2 = KFs[row0 * AKS + kk + j + 4];
            float a3 = KFs[(row0 + 8) * AKS + kk + j + 4];
            #pragma unroll
            for (int ni = 0; ni < 8; ni++) {
                int nc = ni * 8 + lr4;
                float b0 = Vs[(kk + j) * AKS + nc];
                float b1 = Vs[(kk + j + 4) * AKS + nc];
                mma_tf32f(oacc[ni], a0, a1, a2, a3, b0, b1);
            }
        }
    }

    den0 += __shfl_xor_sync(0xffffffff, den0, 1);
    den0 += __shfl_xor_sync(0xffffffff, den0, 2);
    den1 += __shfl_xor_sync(0xffffffff, den1, 1);
    den1 += __shfl_xor_sync(0xffffffff, den1, 2);
    float di0 = 1.0f / (den0 + 1e-6f);
    float di1 = 1.0f / (den1 + 1e-6f);

    float* olo = ao + (size_t)(b * SEQ + r0 + row0) * DIMC + h * HD;
    float* ohi = olo + 8 * DIMC;
    #pragma unroll
    for (int ni = 0; ni < 8; ni++) {
        int cc = ni * 8 + 2 * j;
        *(float2*)(olo + cc) = make_float2(tf32r(oacc[ni][0] * di0), tf32r(oacc[ni][1] * di0));
        *(float2*)(ohi + cc) = make_float2(tf32r(oacc[ni][2] * di1), tf32r(oacc[ni][3] * di1));
    }
}

// ============================================================
// launch
// ============================================================
extern "C" void kernel_launch(void* const* d_in, const int* in_sizes, int n_in,
                              void* d_out, int out_size) {
    const float* x      = (const float*)d_in[0];
    const float* qkv_w  = (const float*)d_in[1];
    const float* proj_w = (const float*)d_in[2];
    const float* proj_b = (const float*)d_in[3];
    const float* alpha  = (const float*)d_in[4];
    const float* beta   = (const float*)d_in[5];
    const float* gamma  = (const float*)d_in[6];
    const float* ln1_w  = (const float*)d_in[7];
    const float* ln1_b  = (const float*)d_in[8];
    const float* ln2_w  = (const float*)d_in[9];
    const float* ln2_b  = (const float*)d_in[10];
    const float* w1     = (const float*)d_in[11];
    const float* b1     = (const float*)d_in[12];
    const float* w2     = (const float*)d_in[13];
    const float* b2     = (const float*)d_in[14];
    float* out = (float*)d_out;

    float *h, *qkv, *ao, *x1, *m, *wq, *wp, *ww1, *ww2;
    cudaGetSymbolAddress((void**)&h,   g_h);
    cudaGetSymbolAddress((void**)&qkv, g_qkv);
    cudaGetSymbolAddress((void**)&ao,  g_ao);
    cudaGetSymbolAddress((void**)&x1,  g_x1);
    cudaGetSymbolAddress((void**)&m,   g_m);
    cudaGetSymbolAddress((void**)&wq,  g_wq);
    cudaGetSymbolAddress((void**)&wp,  g_wp);
    cudaGetSymbolAddress((void**)&ww1, g_w1);
    cudaGetSymbolAddress((void**)&ww2, g_w2);

    cudaFuncSetAttribute(gemm_tc<0>, cudaFuncAttributeMaxDynamicSharedMemorySize, GEMM_SMEM);
    cudaFuncSetAttribute(gemm_tc<1>, cudaFuncAttributeMaxDynamicSharedMemorySize, GEMM_SMEM);
    cudaFuncSetAttribute(gemm_tc<2>, cudaFuncAttributeMaxDynamicSharedMemorySize, GEMM_SMEM);

    // 0. round weights to tf32 (once per launch; deterministic)
    round_w<<<(NW_1 + 255) / 256, 256>>>(qkv_w, wq, proj_w, wp, w1, ww1, w2, ww2);
    // 1. LN1 (tf32-rounded output)
    ln_kernel<<<M_TOT, 128>>>(x, ln1_w, ln1_b, h);
    // 2. QKV projection (tf32-rounded output)
    gemm_tc<0><<<dim3(3 * DIMC / 128, M_TOT / 128), 256, GEMM_SMEM>>>(
        h, wq, nullptr, nullptr, qkv, M_TOT, 3 * DIMC, DIMC);
    // 3. attention (tf32-rounded output)
    attn_tc<<<dim3(SEQ / 64, BATCH * NH), 128>>>(qkv, alpha, beta, gamma, ao);
    // 4. proj + bias + residual (fp32 out)
    gemm_tc<1><<<dim3(DIMC / 128, M_TOT / 128), 256, GEMM_SMEM>>>(
        ao, wp, proj_b, x, x1, M_TOT, DIMC, DIMC);
    // 5. LN2
    ln_kernel<<<M_TOT, 128>>>(x1, ln2_w, ln2_b, h);
    // 6. MLP fc1 + bias + GELU (tf32-rounded output)
    gemm_tc<2><<<dim3(MLPD / 128, M_TOT / 128), 256, GEMM_SMEM>>>(
        h, ww1, b1, nullptr, m, M_TOT, MLPD, DIMC);
    // 7. MLP fc2 + bias + residual (fp32 out)
    gemm_tc<1><<<dim3(DIMC / 128, M_TOT / 128), 256, GEMM_SMEM>>>(
        m, ww2, b2, x1, out, M_TOT, DIMC, MLPD);
}

// round 5
// speedup vs baseline: 1.7626x; 1.0380x over previous
#include <cuda_runtime.h>
#include <math.h>
#include <stdint.h>

#define DIMC 384
#define NH 6
#define HD 64
#define MLPD 1536
#define BATCH 8
#define SEQ 1024
#define M_TOT (BATCH*SEQ)
#define LN_EPS 1e-5f

#define NW_QKV (3*DIMC*DIMC)
#define NW_PROJ (DIMC*DIMC)
#define NW_1 (MLPD*DIMC)
#define NW_2 (DIMC*MLPD)

__device__ float g_h[M_TOT * DIMC];
__device__ float g_qkv[M_TOT * 3 * DIMC];
__device__ float g_ao[M_TOT * DIMC];
__device__ float g_x1[M_TOT * DIMC];
__device__ float g_m[M_TOT * MLPD];
__device__ float g_wq[NW_QKV];
__device__ float g_wp[NW_PROJ];
__device__ float g_w1[NW_1];
__device__ float g_w2[NW_2];

__device__ __forceinline__ float tf32r(float x) {
    float y; asm("cvt.rna.tf32.f32 %0, %1;" : "=f"(y) : "f"(x)); return y;
}

__device__ __forceinline__ void mma_tf32f(float c[4], float a0, float a1,
                                          float a2, float a3, float b0, float b1) {
    asm volatile(
        "mma.sync.aligned.m16n8k8.row.col.f32.tf32.tf32.f32 "
        "{%0,%1,%2,%3},{%4,%5,%6,%7},{%8,%9},{%0,%1,%2,%3};\n"
        : "+f"(c[0]), "+f"(c[1]), "+f"(c[2]), "+f"(c[3])
        : "r"(__float_as_uint(a0)), "r"(__float_as_uint(a1)),
          "r"(__float_as_uint(a2)), "r"(__float_as_uint(a3)),
          "r"(__float_as_uint(b0)), "r"(__float_as_uint(b1)));
}

__device__ __forceinline__ void cpa16(uint32_t s, const void* g) {
    asm volatile("cp.async.cg.shared.global [%0], [%1], 16;" :: "r"(s), "l"(g));
}

// ============================================================
// one-shot weight rounding to tf32
// ============================================================
__global__ __launch_bounds__(256)
void round_w(const float* __restrict__ a, float* __restrict__ oa,
             const float* __restrict__ b, float* __restrict__ ob,
             const float* __restrict__ c, float* __restrict__ oc,
             const float* __restrict__ d, float* __restrict__ od) {
    int i = blockIdx.x * 256 + threadIdx.x;
    if (i < NW_QKV)  oa[i] = tf32r(a[i]);
    if (i < NW_PROJ) ob[i] = tf32r(b[i]);
    if (i < NW_1) { oc[i] = tf32r(c[i]); od[i] = tf32r(d[i]); }
}

// ============================================================
// LayerNorm: one warp per row (384 = 32*12), 8 rows per CTA
// ============================================================
__global__ __launch_bounds__(256)
void ln_kernel(const float* __restrict__ x, const float* __restrict__ w,
               const float* __restrict__ b, float* __restrict__ out) {
    int lane = threadIdx.x & 31;
    int row = blockIdx.x * 8 + (threadIdx.x >> 5);
    const float* xr = x + (size_t)row * DIMC;

    float v[12];
    float s = 0.f;
    #pragma unroll
    for (int i = 0; i < 12; i++) { v[i] = xr[lane + 32 * i]; s += v[i]; }
    #pragma unroll
    for (int o = 16; o > 0; o >>= 1) s += __shfl_xor_sync(0xffffffff, s, o);
    float mean = s * (1.0f / DIMC);

    float q = 0.f;
    #pragma unroll
    for (int i = 0; i < 12; i++) { float d = v[i] - mean; q += d * d; }
    #pragma unroll
    for (int o = 16; o > 0; o >>= 1) q += __shfl_xor_sync(0xffffffff, q, o);
    float r = rsqrtf(q * (1.0f / DIMC) + LN_EPS);

    float* orow = out + (size_t)row * DIMC;
    #pragma unroll
    for (int i = 0; i < 12; i++) {
        int c = lane + 32 * i;
        orow[c] = tf32r((v[i] - mean) * r * w[c] + b[c]);
    }
}

// ============================================================
// TF32 TC GEMM: C[M,N] = A[M,K] @ W[N,K]^T (+epilogue)
// A/W tf32-rounded in gmem -> raw cp.async staging.
// 128x128 tile, BK=32, 3-stage pipeline, 256 thr, warps 2x4.
// smem stride 36 -> banks 4*lr4+j conflict-free.
// ============================================================
#define AST 36
#define SLOT (128*AST)
#define GEMM_SMEM (6 * SLOT * 4)     // 110592 B

template <int EPI>
__global__ __launch_bounds__(256, 2)
void gemm_tc(const float* __restrict__ A, const float* __restrict__ W,
             const float* __restrict__ bias, const float* __restrict__ res,
             float* __restrict__ C, int M, int N, int K) {
    extern __shared__ float smem[];
    float* As = smem;
    float* Bs = smem + 3 * SLOT;
    uint32_t As_u = (uint32_t)__cvta_generic_to_shared(As);
    uint32_t Bs_u = (uint32_t)__cvta_generic_to_shared(Bs);

    int tid = threadIdx.x;
    int lane = tid & 31, wid = tid >> 5;
    int wm = wid >> 2, wn = wid & 3;
    int j = lane & 3, lr4 = lane >> 2;
    int m0 = blockIdx.y * 128, n0 = blockIdx.x * 128;

    int row = tid >> 1;
    int goff = (tid & 1) * 16;          // float offset within 32-float row chunk
    const float* Ag = A + (size_t)(m0 + row) * K + goff;
    const float* Wg = W + (size_t)(n0 + row) * K + goff;
    uint32_t sa_off = (row * AST + goff) * 4;

    float acc[4][4][4] = {};
    int T = K / 32;

    #pragma unroll
    for (int s = 0; s < 2; s++) {
        uint32_t ab = As_u + s * SLOT * 4 + sa_off;
        uint32_t bb = Bs_u + s * SLOT * 4 + sa_off;
        #pragma unroll
        for (int i = 0; i < 4; i++) {
            cpa16(ab + i * 16, Ag + s * 32 + i * 4);
            cpa16(bb + i * 16, Wg + s * 32 + i * 4);
        }
        asm volatile("cp.async.commit_group;");
    }

    for (int t = 0; t < T; t++) {
        if (t < T - 1) asm volatile("cp.async.wait_group 1;");
        else           asm volatile("cp.async.wait_group 0;");
        __syncthreads();
        if (t + 2 < T) {
            int sl = (t + 2) % 3;
            uint32_t ab = As_u + sl * SLOT * 4 + sa_off;
            uint32_t bb = Bs_u + sl * SLOT * 4 + sa_off;
            const float* Ap2 = Ag + (t + 2) * 32;
            const float* Wp2 = Wg + (t + 2) * 32;
            #pragma unroll
            for (int i = 0; i < 4; i++) {
                cpa16(ab + i * 16, Ap2 + i * 4);
                cpa16(bb + i * 16, Wp2 + i * 4);
            }
            asm volatile("cp.async.commit_group;");
        }
        const float* Ast = As + (t % 3) * SLOT;
        const float* Bst = Bs + (t % 3) * SLOT;
        #pragma unroll
        for (int kk = 0; kk < 32; kk += 8) {
            float af[4][4];
            #pragma unroll
            for (int mi = 0; mi < 4; mi++) {
                int mr = wm * 64 + mi * 16 + lr4;
                af[mi][0] = Ast[mr * AST + kk + j];
                af[mi][1] = Ast[(mr + 8) * AST + kk + j];
                af[mi][2] = Ast[mr * AST + kk + j + 4];
                af[mi][3] = Ast[(mr + 8) * AST + kk + j + 4];
            }
            #pragma unroll
            for (int ni = 0; ni < 4; ni++) {
                int nr = wn * 32 + ni * 8 + lr4;
                float b0 = Bst[nr * AST + kk + j];
                float b1 = Bst[nr * AST + kk + j + 4];
                #pragma unroll
                for (int mi = 0; mi < 4; mi++)
                    mma_tf32f(acc[mi][ni], af[mi][0], af[mi][1],
                              af[mi][2], af[mi][3], b0, b1);
            }
        }
    }

    #pragma unroll
    for (int mi = 0; mi < 4; mi++) {
        int r = m0 + wm * 64 + mi * 16 + lr4;
        #pragma unroll
        for (int ni = 0; ni < 4; ni++) {
            int c = n0 + wn * 32 + ni * 8 + 2 * j;
            float v[4] = {acc[mi][ni][0], acc[mi][ni][1], acc[mi][ni][2], acc[mi][ni][3]};
            int rr[2] = {r, r + 8};
            #pragma unroll
            for (int half = 0; half < 2; half++) {
                float x0 = v[half * 2 + 0], x1 = v[half * 2 + 1];
                if (EPI == 0) { x0 = tf32r(x0); x1 = tf32r(x1); }
                if (EPI == 1) {
                    x0 += bias[c] + res[(size_t)rr[half] * N + c];
                    x1 += bias[c + 1] + res[(size_t)rr[half] * N + c + 1];
                }
                if (EPI == 2) {
                    x0 += bias[c];
                    x1 += bias[c + 1];
                    x0 = tf32r(0.5f * x0 * (1.0f + erff(x0 * 0.70710678118654752f)));
                    x1 = tf32r(0.5f * x1 * (1.0f + erff(x1 * 0.70710678118654752f)));
                }
                *(float2*)(C + (size_t)rr[half] * N + c) = make_float2(x0, x1);
            }
        }
    }
}

// ============================================================
// L2Q attention: 256 thr / 8 warps, Q tile 128 rows, K tile 64.
// Double-buffered K/V via cp.async (1 barrier + 1 wait / tile).
// F via warp-private smem pad (+__syncwarp only).
// ============================================================
#define AKS 68
#define KV_TILE (64*AKS)
#define ATTN_SMEM ((4*KV_TILE + 8*16*AKS) * 4)   // 104448 B

__global__ __launch_bounds__(256, 2)
void attn_tc(const float* __restrict__ qkv,
             const float* __restrict__ alpha, const float* __restrict__ beta,
             const float* __restrict__ gamma, float* __restrict__ ao) {
    extern __shared__ float sm[];
    float* Ks = sm;                      // [2][KV_TILE]
    float* Vs = sm + 2 * KV_TILE;        // [2][KV_TILE]
    float* Fw = sm + 4 * KV_TILE;        // [8][16*AKS]
    uint32_t Ks_u = (uint32_t)__cvta_generic_to_shared(Ks);
    uint32_t Vs_u = (uint32_t)__cvta_generic_to_shared(Vs);

    int tid = threadIdx.x, lane = tid & 31, wid = tid >> 5;
    int j = lane & 3, lr4 = lane >> 2;
    int bh = blockIdx.y;
    int b = bh / NH, h = bh % NH;
    int r0 = blockIdx.x * 128;
    float al = alpha[h], be = beta[h], ga = gamma[h];

    const float* qbase = qkv + (size_t)b * SEQ * (3 * DIMC) + h * HD;
    const float* kbase = qbase + DIMC;
    const float* vbase = qbase + 2 * DIMC;

    int row0 = wid * 16 + lr4;
    float* fw = Fw + wid * 16 * AKS;

    // Q fragments in registers (qkv already tf32-rounded)
    float qf[8][4];
    {
        const float* qlo = qbase + (size_t)(r0 + row0) * (3 * DIMC);
        const float* qhi = qlo + 8 * (3 * DIMC);
        #pragma unroll
        for (int dk = 0; dk < 8; dk++) {
            qf[dk][0] = qlo[dk * 8 + j];
            qf[dk][1] = qhi[dk * 8 + j];
            qf[dk][2] = qlo[dk * 8 + j + 4];
            qf[dk][3] = qhi[dk * 8 + j + 4];
        }
    }

    float oacc[8][4];
    #pragma unroll
    for (int i = 0; i < 8; i++)
        #pragma unroll
        for (int r = 0; r < 4; r++) oacc[i][r] = 0.f;
    float den0 = 0.f, den1 = 0.f;

    // loader mapping: 256 thr, 64 rows x 64 floats; 16 floats/thread
    int lrow = tid >> 2;
    int lq = (tid & 3) * 16;
    uint32_t s_off = (lrow * AKS + lq) * 4;

    // prologue: tile 0 into buffer 0
    {
        const float* kr = kbase + (size_t)lrow * (3 * DIMC) + lq;
        const float* vr = vbase + (size_t)lrow * (3 * DIMC) + lq;
        #pragma unroll
        for (int i = 0; i < 4; i++) {
            cpa16(Ks_u + s_off + i * 16, kr + i * 4);
            cpa16(Vs_u + s_off + i * 16, vr + i * 4);
        }
        asm volatile("cp.async.commit_group;");
    }

    const int NT = SEQ / 64;
    for (int t = 0; t < NT; t++) {
        int s = t & 1;
        asm volatile("cp.async.wait_group 0;");
        __syncthreads();
        if (t + 1 < NT) {
            int s2 = s ^ 1;
            const float* kr = kbase + (size_t)((t + 1) * 64 + lrow) * (3 * DIMC) + lq;
            const float* vr = vbase + (size_t)((t + 1) * 64 + lrow) * (3 * DIMC) + lq;
            uint32_t kb = Ks_u + s2 * KV_TILE * 4 + s_off;
            uint32_t vb = Vs_u + s2 * KV_TILE * 4 + s_off;
            #pragma unroll
            for (int i = 0; i < 4; i++) {
                cpa16(kb + i * 16, kr + i * 4);
                cpa16(vb + i * 16, vr + i * 4);
            }
            asm volatile("cp.async.commit_group;");
        }
        const float* Kt = Ks + s * KV_TILE;
        const float* Vt = Vs + s * KV_TILE;

        // S = Q K^T  (per warp: 16 rows x 64 keys)
        float sacc[8][4];
        #pragma unroll
        for (int i = 0; i < 8; i++)
            #pragma unroll
            for (int r = 0; r < 4; r++) sacc[i][r] = 0.f;

        #pragma unroll
        for (int kk = 0; kk < 64; kk += 8) {
            int dk = kk >> 3;
            #pragma unroll
            for (int ni = 0; ni < 8; ni++) {
                int br = ni * 8 + lr4;
                float b0 = Kt[br * AKS + kk + j];
                float b1 = Kt[br * AKS + kk + j + 4];
                mma_tf32f(sacc[ni], qf[dk][0], qf[dk][1], qf[dk][2], qf[dk][3], b0, b1);
            }
        }

        // transform + write F to warp-private pad
        #pragma unroll
        for (int ni = 0; ni < 8; ni++) {
            int cc = ni * 8 + 2 * j;
            float s0 = sacc[ni][0] * 0.125f;
            float s1 = sacc[ni][1] * 0.125f;
            float s2 = sacc[ni][2] * 0.125f;
            float s3 = sacc[ni][3] * 0.125f;
            float f0 = fmaxf(fmaf(al * s0, s0, fmaf(be, s0, ga)), 0.f);
            float f1 = fmaxf(fmaf(al * s1, s1, fmaf(be, s1, ga)), 0.f);
            float f2 = fmaxf(fmaf(al * s2, s2, fmaf(be, s2, ga)), 0.f);
            float f3 = fmaxf(fmaf(al * s3, s3, fmaf(be, s3, ga)), 0.f);
            den0 += f0 + f1;
            den1 += f2 + f3;
            fw[lr4 * AKS + cc]           = tf32r(f0);
            fw[lr4 * AKS + cc + 1]       = tf32r(f1);
            fw[(lr4 + 8) * AKS + cc]     = tf32r(f2);
            fw[(lr4 + 8) * AKS + cc + 1] = tf32r(f3);
        }
        __syncwarp();

        // O += F V
        #pragma unroll
        for (int kk = 0; kk < 64; kk += 8) {
            float a0 = fw[lr4 * AKS + kk + j];
            float a1 = fw[(lr4 + 8) * AKS + kk + j];
            float a2 = fw[lr4 * AKS + kk + j + 4];
            float a3 = fw[(lr4 + 8) * AKS + kk + j + 4];
            #pragma unroll
            for (int ni = 0; ni < 8; ni++) {
                int nc = ni * 8 + lr4;
                float b0 = Vt[(kk + j) * AKS + nc];
                float b1 = Vt[(kk + j + 4) * AKS + nc];
                mma_tf32f(oacc[ni], a0, a1, a2, a3, b0, b1);
            }
        }
        __syncwarp();   // F pad reuse next tile
    }

    den0 += __shfl_xor_sync(0xffffffff, den0, 1);
    den0 += __shfl_xor_sync(0xffffffff, den0, 2);
    den1 += __shfl_xor_sync(0xffffffff, den1, 1);
    den1 += __shfl_xor_sync(0xffffffff, den1, 2);
    float di0 = 1.0f / (den0 + 1e-6f);
    float di1 = 1.0f / (den1 + 1e-6f);

    float* olo = ao + (size_t)(b * SEQ + r0 + row0) * DIMC + h * HD;
    float* ohi = olo + 8 * DIMC;
    #pragma unroll
    for (int ni = 0; ni < 8; ni++) {
        int cc = ni * 8 + 2 * j;
        *(float2*)(olo + cc) = make_float2(tf32r(oacc[ni][0] * di0), tf32r(oacc[ni][1] * di0));
        *(float2*)(ohi + cc) = make_float2(tf32r(oacc[ni][2] * di1), tf32r(oacc[ni][3] * di1));
    }
}

// ============================================================
// launch
// ============================================================
extern "C" void kernel_launch(void* const* d_in, const int* in_sizes, int n_in,
                              void* d_out, int out_size) {
    const float* x      = (const float*)d_in[0];
    const float* qkv_w  = (const float*)d_in[1];
    const float* proj_w = (const float*)d_in[2];
    const float* proj_b = (const float*)d_in[3];
    const float* alpha  = (const float*)d_in[4];
    const float* beta   = (const float*)d_in[5];
    const float* gamma  = (const float*)d_in[6];
    const float* ln1_w  = (const float*)d_in[7];
    const float* ln1_b  = (const float*)d_in[8];
    const float* ln2_w  = (const float*)d_in[9];
    const float* ln2_b  = (const float*)d_in[10];
    const float* w1     = (const float*)d_in[11];
    const float* b1     = (const float*)d_in[12];
    const float* w2     = (const float*)d_in[13];
    const float* b2     = (const float*)d_in[14];
    float* out = (float*)d_out;

    float *h, *qkv, *ao, *x1, *m, *wq, *wp, *ww1, *ww2;
    cudaGetSymbolAddress((void**)&h,   g_h);
    cudaGetSymbolAddress((void**)&qkv, g_qkv);
    cudaGetSymbolAddress((void**)&ao,  g_ao);
    cudaGetSymbolAddress((void**)&x1,  g_x1);
    cudaGetSymbolAddress((void**)&m,   g_m);
    cudaGetSymbolAddress((void**)&wq,  g_wq);
    cudaGetSymbolAddress((void**)&wp,  g_wp);
    cudaGetSymbolAddress((void**)&ww1, g_w1);
    cudaGetSymbolAddress((void**)&ww2, g_w2);

    cudaFuncSetAttribute(gemm_tc<0>, cudaFuncAttributeMaxDynamicSharedMemorySize, GEMM_SMEM);
    cudaFuncSetAttribute(gemm_tc<1>, cudaFuncAttributeMaxDynamicSharedMemorySize, GEMM_SMEM);
    cudaFuncSetAttribute(gemm_tc<2>, cudaFuncAttributeMaxDynamicSharedMemorySize, GEMM_SMEM);
    cudaFuncSetAttribute(attn_tc,    cudaFuncAttributeMaxDynamicSharedMemorySize, ATTN_SMEM);

    round_w<<<(NW_1 + 255) / 256, 256>>>(qkv_w, wq, proj_w, wp, w1, ww1, w2, ww2);
    ln_kernel<<<M_TOT / 8, 256>>>(x, ln1_w, ln1_b, h);
    gemm_tc<0><<<dim3(3 * DIMC / 128, M_TOT / 128), 256, GEMM_SMEM>>>(
        h, wq, nullptr, nullptr, qkv, M_TOT, 3 * DIMC, DIMC);
    attn_tc<<<dim3(SEQ / 128, BATCH * NH), 256, ATTN_SMEM>>>(qkv, alpha, beta, gamma, ao);
    gemm_tc<1><<<dim3(DIMC / 128, M_TOT / 128), 256, GEMM_SMEM>>>(
        ao, wp, proj_b, x, x1, M_TOT, DIMC, DIMC);
    ln_kernel<<<M_TOT / 8, 256>>>(x1, ln2_w, ln2_b, h);
    gemm_tc<2><<<dim3(MLPD / 128, M_TOT / 128), 256, GEMM_SMEM>>>(
        h, ww1, b1, nullptr, m, M_TOT, MLPD, DIMC);
    gemm_tc<1><<<dim3(DIMC / 128, M_TOT / 128), 256, GEMM_SMEM>>>(
        m, ww2, b2, x1, out, M_TOT, DIMC, MLPD);
}

// round 7
// speedup vs baseline: 1.8436x; 1.0460x over previous
#include <cuda_runtime.h>
#include <math.h>
#include <stdint.h>

#define DIMC 384
#define NH 6
#define HD 64
#define MLPD 1536
#define BATCH 8
#define SEQ 1024
#define M_TOT (BATCH*SEQ)
#define LN_EPS 1e-5f

#define NW_QKV (3*DIMC*DIMC)
#define NW_PROJ (DIMC*DIMC)
#define NW_1 (MLPD*DIMC)
#define NW_2 (DIMC*MLPD)

__device__ float g_h[M_TOT * DIMC];
__device__ float g_qkv[M_TOT * 3 * DIMC];
__device__ float g_ao[M_TOT * DIMC];
__device__ float g_x1[M_TOT * DIMC];
__device__ float g_m[M_TOT * MLPD];
__device__ float g_wq[NW_QKV];
__device__ float g_wp[NW_PROJ];
__device__ float g_w1[NW_1];
__device__ float g_w2[NW_2];

__device__ __forceinline__ float tf32r(float x) {
    float y; asm("cvt.rna.tf32.f32 %0, %1;" : "=f"(y) : "f"(x)); return y;
}

// pair permutation: element k of an 8-group goes to slot (k%4)*2 + k/4,
// so a v2 load at offset 2j yields (j, j+4) = one tf32 fragment pair.
__device__ __forceinline__ int perm8(int c) {
    return (c & ~7) | ((c & 3) << 1) | ((c >> 2) & 1);
}

__device__ __forceinline__ void mma_tf32f(float c[4], float a0, float a1,
                                          float a2, float a3, float b0, float b1) {
    asm volatile(
        "mma.sync.aligned.m16n8k8.row.col.f32.tf32.tf32.f32 "
        "{%0,%1,%2,%3},{%4,%5,%6,%7},{%8,%9},{%0,%1,%2,%3};\n"
        : "+f"(c[0]), "+f"(c[1]), "+f"(c[2]), "+f"(c[3])
        : "r"(__float_as_uint(a0)), "r"(__float_as_uint(a1)),
          "r"(__float_as_uint(a2)), "r"(__float_as_uint(a3)),
          "r"(__float_as_uint(b0)), "r"(__float_as_uint(b1)));
}

__device__ __forceinline__ void cpa16(uint32_t s, const void* g) {
    asm volatile("cp.async.cg.shared.global [%0], [%1], 16;" :: "r"(s), "l"(g));
}

// ============================================================
// one-shot weight rounding to tf32 + pair permutation along K
// (row lengths are multiples of 8, so flat perm8 == per-row perm8)
// ============================================================
__global__ __launch_bounds__(256)
void round_w(const float* __restrict__ a, float* __restrict__ oa,
             const float* __restrict__ b, float* __restrict__ ob,
             const float* __restrict__ c, float* __restrict__ oc,
             const float* __restrict__ d, float* __restrict__ od) {
    int i = blockIdx.x * 256 + threadIdx.x;
    int p = perm8(i);
    if (i < NW_QKV)  oa[p] = tf32r(a[i]);
    if (i < NW_PROJ) ob[p] = tf32r(b[i]);
    if (i < NW_1) { oc[p] = tf32r(c[i]); od[p] = tf32r(d[i]); }
}

// ============================================================
// LayerNorm: one warp per row; output pair-permuted (feeds GEMM A)
// ============================================================
__global__ __launch_bounds__(256)
void ln_kernel(const float* __restrict__ x, const float* __restrict__ w,
               const float* __restrict__ b, float* __restrict__ out) {
    int lane = threadIdx.x & 31;
    int row = blockIdx.x * 8 + (threadIdx.x >> 5);
    const float* xr = x + (size_t)row * DIMC;

    float v[12];
    float s = 0.f;
    #pragma unroll
    for (int i = 0; i < 12; i++) { v[i] = xr[lane + 32 * i]; s += v[i]; }
    #pragma unroll
    for (int o = 16; o > 0; o >>= 1) s += __shfl_xor_sync(0xffffffff, s, o);
    float mean = s * (1.0f / DIMC);

    float q = 0.f;
    #pragma unroll
    for (int i = 0; i < 12; i++) { float d = v[i] - mean; q += d * d; }
    #pragma unroll
    for (int o = 16; o > 0; o >>= 1) q += __shfl_xor_sync(0xffffffff, q, o);
    float r = rsqrtf(q * (1.0f / DIMC) + LN_EPS);

    float* orow = out + (size_t)row * DIMC;
    #pragma unroll
    for (int i = 0; i < 12; i++) {
        int c = lane + 32 * i;
        orow[perm8(c)] = tf32r((v[i] - mean) * r * w[c] + b[c]);
    }
}

// ============================================================
// TF32 TC GEMM: C[M,N] = A[M,K] @ W[N,K]^T (+epilogue)
// A/W pre-rounded AND pair-permuted in gmem -> raw cp.async,
// every fragment load is LDS.64 (stride 40: conflict-free v2).
// MT x 128 tile, BK=32, 2-stage pipeline, 256 thr, warps 2x4.
// EPI 0: qkv out (Q/K sections perm8, V natural), tf32-rounded
// EPI 1: +bias +res, fp32 natural
// EPI 2: +bias, exact GELU, tf32-rounded, perm8 (feeds fc2 A)
// ============================================================
#define PST 40
#define GEMM_SMEM(MT) (2 * ((MT) + 128) * PST * 4)

template <int EPI, int MT>
__global__ __launch_bounds__(256, 2)
void gemm_tc(const float* __restrict__ A, const float* __restrict__ W,
             const float* __restrict__ bias, const float* __restrict__ res,
             float* __restrict__ C, int M, int N, int K) {
    extern __shared__ float smem[];
    const int ASLOT = MT * PST;
    const int BSLOT = 128 * PST;
    float* As = smem;                    // [2][ASLOT]
    float* Bs = smem + 2 * ASLOT;        // [2][BSLOT]
    uint32_t As_u = (uint32_t)__cvta_generic_to_shared(As);
    uint32_t Bs_u = (uint32_t)__cvta_generic_to_shared(Bs);

    int tid = threadIdx.x;
    int lane = tid & 31, wid = tid >> 5;
    int wm = wid >> 2, wn = wid & 3;
    int j = lane & 3, lr4 = lane >> 2;
    int m0 = blockIdx.y * MT, n0 = blockIdx.x * 128;

    // A loader: TPR threads per row
    const int TPR = 256 / MT;                  // 2 (MT=128) or 4 (MT=64)
    const int FPT = 32 / TPR;                  // floats per thread: 16 or 8
    int arow = tid / TPR;
    int aoff = (tid % TPR) * FPT;
    const float* Ag = A + (size_t)(m0 + arow) * K + aoff;
    uint32_t a_soff = (arow * PST + aoff) * 4;
    // B loader: 2 thr/row
    int brow = tid >> 1;
    int boff = (tid & 1) * 16;
    const float* Wg = W + (size_t)(n0 + brow) * K + boff;
    uint32_t b_soff = (brow * PST + boff) * 4;

    const int MI = MT / 32;
    float acc[MI][4][4];
    #pragma unroll
    for (int mi = 0; mi < MI; mi++)
        #pragma unroll
        for (int ni = 0; ni < 4; ni++)
            #pragma unroll
            for (int r = 0; r < 4; r++) acc[mi][ni][r] = 0.f;

    int T = K / 32;
    // prologue: stage 0
    {
        #pragma unroll
        for (int i = 0; i < FPT / 4; i++) cpa16(As_u + a_soff + i * 16, Ag + i * 4);
        #pragma unroll
        for (int i = 0; i < 4; i++)       cpa16(Bs_u + b_soff + i * 16, Wg + i * 4);
        asm volatile("cp.async.commit_group;");
    }

    for (int t = 0; t < T; t++) {
        asm volatile("cp.async.wait_group 0;");
        __syncthreads();
        if (t + 1 < T) {
            int s2 = (t + 1) & 1;
            const float* ag = Ag + (t + 1) * 32;
            const float* wg = Wg + (t + 1) * 32;
            uint32_t ab = As_u + s2 * ASLOT * 4 + a_soff;
            uint32_t bb = Bs_u + s2 * BSLOT * 4 + b_soff;
            #pragma unroll
            for (int i = 0; i < FPT / 4; i++) cpa16(ab + i * 16, ag + i * 4);
            #pragma unroll
            for (int i = 0; i < 4; i++)       cpa16(bb + i * 16, wg + i * 4);
            asm volatile("cp.async.commit_group;");
        }
        const float* Ast = As + (t & 1) * ASLOT;
        const float* Bst = Bs + (t & 1) * BSLOT;
        #pragma unroll
        for (int kk = 0; kk < 32; kk += 8) {
            float2 af0[MI], af1[MI];
            #pragma unroll
            for (int mi = 0; mi < MI; mi++) {
                int mr = wm * (MT / 2) + mi * 16 + lr4;
                af0[mi] = *(const float2*)&Ast[mr * PST + kk + 2 * j];        // (a0,a2)
                af1[mi] = *(const float2*)&Ast[(mr + 8) * PST + kk + 2 * j];  // (a1,a3)
            }
            #pragma unroll
            for (int ni = 0; ni < 4; ni++) {
                int nr = wn * 32 + ni * 8 + lr4;
                float2 bf = *(const float2*)&Bst[nr * PST + kk + 2 * j];      // (b0,b1)
                #pragma unroll
                for (int mi = 0; mi < MI; mi++)
                    mma_tf32f(acc[mi][ni], af0[mi].x, af1[mi].x,
                              af0[mi].y, af1[mi].y, bf.x, bf.y);
            }
        }
    }

    #pragma unroll
    for (int mi = 0; mi < MI; mi++) {
        int r = m0 + wm * (MT / 2) + mi * 16 + lr4;
        #pragma unroll
        for (int ni = 0; ni < 4; ni++) {
            int c = n0 + wn * 32 + ni * 8 + 2 * j;
            float v[4] = {acc[mi][ni][0], acc[mi][ni][1], acc[mi][ni][2], acc[mi][ni][3]};
            int rr[2] = {r, r + 8};
            #pragma unroll
            for (int half = 0; half < 2; half++) {
                float x0 = v[half * 2 + 0], x1 = v[half * 2 + 1];
                float* cr = C + (size_t)rr[half] * N;
                if (EPI == 0) {
                    // qkv: permute Q/K sections (cols < 768), V natural
                    int d0 = (c < 768) ? perm8(c) : c;
                    int d1 = (c + 1 < 768) ? perm8(c + 1) : (c + 1);
                    cr[d0] = tf32r(x0);
                    cr[d1] = tf32r(x1);
                }
                if (EPI == 1) {
                    const float* rrow = res + (size_t)rr[half] * N;
                    x0 += bias[c] + rrow[c];
                    x1 += bias[c + 1] + rrow[c + 1];
                    *(float2*)(cr + c) = make_float2(x0, x1);
                }
                if (EPI == 2) {
                    x0 += bias[c];
                    x1 += bias[c + 1];
                    cr[perm8(c)]     = tf32r(0.5f * x0 * (1.0f + erff(x0 * 0.70710678118654752f)));
                    cr[perm8(c + 1)] = tf32r(0.5f * x1 * (1.0f + erff(x1 * 0.70710678118654752f)));
                }
            }
        }
    }
}

// ============================================================
// L2Q attention: 256 thr / 8 warps, Q tile 128 rows, K tile 64.
// qkv Q/K sections are pair-permuted -> Q frag LDG.64, K frag LDS.64.
// Smem stride 72: K v2 conflict-free, V scalar conflict-free.
// F pad written pair-permuted -> A-frag LDS.64.
// ============================================================
#define AKS 72
#define KV_TILE (64*AKS)
#define FPAD (16*AKS)
#define ATTN_SMEM ((4*KV_TILE + 8*FPAD) * 4)   // 110592 B

__global__ __launch_bounds__(256, 2)
void attn_tc(const float* __restrict__ qkv,
             const float* __restrict__ alpha, const float* __restrict__ beta,
             const float* __restrict__ gamma, float* __restrict__ ao) {
    extern __shared__ float sm[];
    float* Ks = sm;
    float* Vs = sm + 2 * KV_TILE;
    float* Fw = sm + 4 * KV_TILE;
    uint32_t Ks_u = (uint32_t)__cvta_generic_to_shared(Ks);
    uint32_t Vs_u = (uint32_t)__cvta_generic_to_shared(Vs);

    int tid = threadIdx.x, lane = tid & 31, wid = tid >> 5;
    int j = lane & 3, lr4 = lane >> 2;
    int bh = blockIdx.y;
    int b = bh / NH, h = bh % NH;
    int r0 = blockIdx.x * 128;
    float al = alpha[h], be = beta[h], ga = gamma[h];

    const float* qbase = qkv + (size_t)b * SEQ * (3 * DIMC) + h * HD;
    const float* kbase = qbase + DIMC;
    const float* vbase = qbase + 2 * DIMC;

    int row0 = wid * 16 + lr4;
    float* fw = Fw + wid * FPAD;

    // Q fragments (Q section pair-permuted in gmem -> float2 loads)
    float qf[8][4];
    {
        const float* qlo = qbase + (size_t)(r0 + row0) * (3 * DIMC);
        const float* qhi = qlo + 8 * (3 * DIMC);
        #pragma unroll
        for (int dk = 0; dk < 8; dk++) {
            float2 q0 = *(const float2*)(qlo + dk * 8 + 2 * j);
            float2 q1 = *(const float2*)(qhi + dk * 8 + 2 * j);
            qf[dk][0] = q0.x;  // orig k=j
            qf[dk][1] = q1.x;
            qf[dk][2] = q0.y;  // orig k=j+4
            qf[dk][3] = q1.y;
        }
    }

    float oacc[8][4];
    #pragma unroll
    for (int i = 0; i < 8; i++)
        #pragma unroll
        for (int r = 0; r < 4; r++) oacc[i][r] = 0.f;
    float den0 = 0.f, den1 = 0.f;

    int lrow = tid >> 2;
    int lq = (tid & 3) * 16;
    uint32_t s_off = (lrow * AKS + lq) * 4;

    {
        const float* kr = kbase + (size_t)lrow * (3 * DIMC) + lq;
        const float* vr = vbase + (size_t)lrow * (3 * DIMC) + lq;
        #pragma unroll
        for (int i = 0; i < 4; i++) {
            cpa16(Ks_u + s_off + i * 16, kr + i * 4);
            cpa16(Vs_u + s_off + i * 16, vr + i * 4);
        }
        asm volatile("cp.async.commit_group;");
    }

    const int NT = SEQ / 64;
    for (int t = 0; t < NT; t++) {
        int s = t & 1;
        asm volatile("cp.async.wait_group 0;");
        __syncthreads();
        if (t + 1 < NT) {
            int s2 = s ^ 1;
            const float* kr = kbase + (size_t)((t + 1) * 64 + lrow) * (3 * DIMC) + lq;
            const float* vr = vbase + (size_t)((t + 1) * 64 + lrow) * (3 * DIMC) + lq;
            uint32_t kb = Ks_u + s2 * KV_TILE * 4 + s_off;
            uint32_t vb = Vs_u + s2 * KV_TILE * 4 + s_off;
            #pragma unroll
            for (int i = 0; i < 4; i++) {
                cpa16(kb + i * 16, kr + i * 4);
                cpa16(vb + i * 16, vr + i * 4);
            }
            asm volatile("cp.async.commit_group;");
        }
        const float* Kt = Ks + s * KV_TILE;
        const float* Vt = Vs + s * KV_TILE;

        // S = Q K^T  (K section pair-permuted -> v2 B-frags)
        float sacc[8][4];
        #pragma unroll
        for (int i = 0; i < 8; i++)
            #pragma unroll
            for (int r = 0; r < 4; r++) sacc[i][r] = 0.f;

        #pragma unroll
        for (int kk = 0; kk < 64; kk += 8) {
            int dk = kk >> 3;
            #pragma unroll
            for (int ni = 0; ni < 8; ni++) {
                int br = ni * 8 + lr4;
                float2 bf = *(const float2*)&Kt[br * AKS + kk + 2 * j];
                mma_tf32f(sacc[ni], qf[dk][0], qf[dk][1], qf[dk][2], qf[dk][3],
                          bf.x, bf.y);
            }
        }

        // transform; write F pair-permuted into warp pad
        #pragma unroll
        for (int ni = 0; ni < 8; ni++) {
            int c0 = ni * 8 + 2 * j;
            float s0 = sacc[ni][0] * 0.125f;
            float s1 = sacc[ni][1] * 0.125f;
            float s2 = sacc[ni][2] * 0.125f;
            float s3 = sacc[ni][3] * 0.125f;
            float f0 = fmaxf(fmaf(al * s0, s0, fmaf(be, s0, ga)), 0.f);
            float f1 = fmaxf(fmaf(al * s1, s1, fmaf(be, s1, ga)), 0.f);
            float f2 = fmaxf(fmaf(al * s2, s2, fmaf(be, s2, ga)), 0.f);
            float f3 = fmaxf(fmaf(al * s3, s3, fmaf(be, s3, ga)), 0.f);
            den0 += f0 + f1;
            den1 += f2 + f3;
            int p0 = perm8(c0), p1 = perm8(c0 + 1);
            fw[lr4 * AKS + p0]       = tf32r(f0);
            fw[lr4 * AKS + p1]       = tf32r(f1);
            fw[(lr4 + 8) * AKS + p0] = tf32r(f2);
            fw[(lr4 + 8) * AKS + p1] = tf32r(f3);
        }
        __syncwarp();

        // O += F V  (F paired -> v2 A-frags; V natural, stride-72 conflict-free)
        #pragma unroll
        for (int kk = 0; kk < 64; kk += 8) {
            float2 falo = *(const float2*)&fw[lr4 * AKS + kk + 2 * j];        // (a0,a2)
            float2 fahi = *(const float2*)&fw[(lr4 + 8) * AKS + kk + 2 * j];  // (a1,a3)
            #pragma unroll
            for (int ni = 0; ni < 8; ni++) {
                int nc = ni * 8 + lr4;
                float b0 = Vt[(kk + j) * AKS + nc];
                float b1 = Vt[(kk + j + 4) * AKS + nc];
                mma_tf32f(oacc[ni], falo.x, fahi.x, falo.y, fahi.y, b0, b1);
            }
        }
        __syncwarp();
    }

    den0 += __shfl_xor_sync(0xffffffff, den0, 1);
    den0 += __shfl_xor_sync(0xffffffff, den0, 2);
    den1 += __shfl_xor_sync(0xffffffff, den1, 1);
    den1 += __shfl_xor_sync(0xffffffff, den1, 2);
    float di0 = 1.0f / (den0 + 1e-6f);
    float di1 = 1.0f / (den1 + 1e-6f);

    // output pair-permuted (feeds proj's A operand)
    float* olo = ao + (size_t)(b * SEQ + r0 + row0) * DIMC + h * HD;
    float* ohi = olo + 8 * DIMC;
    #pragma unroll
    for (int ni = 0; ni < 8; ni++) {
        int c0 = ni * 8 + 2 * j;
        int p0 = perm8(c0), p1 = perm8(c0 + 1);
        olo[p0] = tf32r(oacc[ni][0] * di0);
        olo[p1] = tf32r(oacc[ni][1] * di0);
        ohi[p0] = tf32r(oacc[ni][2] * di1);
        ohi[p1] = tf32r(oacc[ni][3] * di1);
    }
}

// ============================================================
// launch
// ============================================================
extern "C" void kernel_launch(void* const* d_in, const int* in_sizes, int n_in,
                              void* d_out, int out_size) {
    const float* x      = (const float*)d_in[0];
    const float* qkv_w  = (const float*)d_in[1];
    const float* proj_w = (const float*)d_in[2];
    const float* proj_b = (const float*)d_in[3];
    const float* alpha  = (const float*)d_in[4];
    const float* beta   = (const float*)d_in[5];
    const float* gamma  = (const float*)d_in[6];
    const float* ln1_w  = (const float*)d_in[7];
    const float* ln1_b  = (const float*)d_in[8];
    const float* ln2_w  = (const float*)d_in[9];
    const float* ln2_b  = (const float*)d_in[10];
    const float* w1     = (const float*)d_in[11];
    const float* b1     = (const float*)d_in[12];
    const float* w2     = (const float*)d_in[13];
    const float* b2     = (const float*)d_in[14];
    float* out = (float*)d_out;

    float *h, *qkv, *ao, *x1, *m, *wq, *wp, *ww1, *ww2;
    cudaGetSymbolAddress((void**)&h,   g_h);
    cudaGetSymbolAddress((void**)&qkv, g_qkv);
    cudaGetSymbolAddress((void**)&ao,  g_ao);
    cudaGetSymbolAddress((void**)&x1,  g_x1);
    cudaGetSymbolAddress((void**)&m,   g_m);
    cudaGetSymbolAddress((void**)&wq,  g_wq);
    cudaGetSymbolAddress((void**)&wp,  g_wp);
    cudaGetSymbolAddress((void**)&ww1, g_w1);
    cudaGetSymbolAddress((void**)&ww2, g_w2);

    cudaFuncSetAttribute((const void*)gemm_tc<0,128>, cudaFuncAttributeMaxDynamicSharedMemorySize, GEMM_SMEM(128));
    cudaFuncSetAttribute((const void*)gemm_tc<2,128>, cudaFuncAttributeMaxDynamicSharedMemorySize, GEMM_SMEM(128));
    cudaFuncSetAttribute((const void*)gemm_tc<1,64>,  cudaFuncAttributeMaxDynamicSharedMemorySize, GEMM_SMEM(64));
    cudaFuncSetAttribute((const void*)attn_tc,        cudaFuncAttributeMaxDynamicSharedMemorySize, ATTN_SMEM);

    round_w<<<(NW_1 + 255) / 256, 256>>>(qkv_w, wq, proj_w, wp, w1, ww1, w2, ww2);
    ln_kernel<<<M_TOT / 8, 256>>>(x, ln1_w, ln1_b, h);
    gemm_tc<0,128><<<dim3(3 * DIMC / 128, M_TOT / 128), 256, GEMM_SMEM(128)>>>(
        h, wq, nullptr, nullptr, qkv, M_TOT, 3 * DIMC, DIMC);
    attn_tc<<<dim3(SEQ / 128, BATCH * NH), 256, ATTN_SMEM>>>(qkv, alpha, beta, gamma, ao);
    gemm_tc<1,64><<<dim3(DIMC / 128, M_TOT / 64), 256, GEMM_SMEM(64)>>>(
        ao, wp, proj_b, x, x1, M_TOT, DIMC, DIMC);
    ln_kernel<<<M_TOT / 8, 256>>>(x1, ln2_w, ln2_b, h);
    gemm_tc<2,128><<<dim3(MLPD / 128, M_TOT / 128), 256, GEMM_SMEM(128)>>>(
        h, ww1, b1, nullptr, m, M_TOT, MLPD, DIMC);
    gemm_tc<1,64><<<dim3(DIMC / 128, M_TOT / 64), 256, GEMM_SMEM(64)>>>(
        m, ww2, b2, x1, out, M_TOT, DIMC, MLPD);
}

// round 8
// speedup vs baseline: 1.8622x; 1.0101x over previous
#include <cuda_runtime.h>
#include <math.h>
#include <stdint.h>

#define DIMC 384
#define NH 6
#define HD 64
#define MLPD 1536
#define BATCH 8
#define SEQ 1024
#define M_TOT (BATCH*SEQ)
#define LN_EPS 1e-5f

#define NW_QKV (3*DIMC*DIMC)
#define NW_PROJ (DIMC*DIMC)
#define NW_1 (MLPD*DIMC)
#define NW_2 (DIMC*MLPD)

__device__ float g_h[M_TOT * DIMC];
__device__ float g_qkv[M_TOT * 3 * DIMC];
__device__ float g_vt[BATCH * NH * HD * SEQ];
__device__ float g_ao[M_TOT * DIMC];
__device__ float g_x1[M_TOT * DIMC];
__device__ float g_m[M_TOT * MLPD];
__device__ float g_wq[NW_QKV];
__device__ float g_wp[NW_PROJ];
__device__ float g_w1[NW_1];
__device__ float g_w2[NW_2];

__device__ __forceinline__ float tf32r(float x) {
    float y; asm("cvt.rna.tf32.f32 %0, %1;" : "=f"(y) : "f"(x)); return y;
}

// pair permutation: element k of an 8-group -> slot (k%4)*2 + k/4,
// so a v2 load at offset 2j yields (j, j+4) = one tf32 fragment pair.
__device__ __forceinline__ int perm8(int c) {
    return (c & ~7) | ((c & 3) << 1) | ((c >> 2) & 1);
}

__device__ __forceinline__ void mma_tf32f(float c[4], float a0, float a1,
                                          float a2, float a3, float b0, float b1) {
    asm volatile(
        "mma.sync.aligned.m16n8k8.row.col.f32.tf32.tf32.f32 "
        "{%0,%1,%2,%3},{%4,%5,%6,%7},{%8,%9},{%0,%1,%2,%3};\n"
        : "+f"(c[0]), "+f"(c[1]), "+f"(c[2]), "+f"(c[3])
        : "r"(__float_as_uint(a0)), "r"(__float_as_uint(a1)),
          "r"(__float_as_uint(a2)), "r"(__float_as_uint(a3)),
          "r"(__float_as_uint(b0)), "r"(__float_as_uint(b1)));
}

__device__ __forceinline__ void cpa16(uint32_t s, const void* g) {
    asm volatile("cp.async.cg.shared.global [%0], [%1], 16;" :: "r"(s), "l"(g));
}

// ============================================================
// one-shot weight rounding to tf32 + pair permutation along K
// ============================================================
__global__ __launch_bounds__(256)
void round_w(const float* __restrict__ a, float* __restrict__ oa,
             const float* __restrict__ b, float* __restrict__ ob,
             const float* __restrict__ c, float* __restrict__ oc,
             const float* __restrict__ d, float* __restrict__ od) {
    int i = blockIdx.x * 256 + threadIdx.x;
    int p = perm8(i);
    if (i < NW_QKV)  oa[p] = tf32r(a[i]);
    if (i < NW_PROJ) ob[p] = tf32r(b[i]);
    if (i < NW_1) { oc[p] = tf32r(c[i]); od[p] = tf32r(d[i]); }
}

// ============================================================
// LayerNorm: one warp per row; output pair-permuted (feeds GEMM A)
// ============================================================
__global__ __launch_bounds__(256)
void ln_kernel(const float* __restrict__ x, const float* __restrict__ w,
               const float* __restrict__ b, float* __restrict__ out) {
    int lane = threadIdx.x & 31;
    int row = blockIdx.x * 8 + (threadIdx.x >> 5);
    const float* xr = x + (size_t)row * DIMC;

    float v[12];
    float s = 0.f;
    #pragma unroll
    for (int i = 0; i < 12; i++) { v[i] = xr[lane + 32 * i]; s += v[i]; }
    #pragma unroll
    for (int o = 16; o > 0; o >>= 1) s += __shfl_xor_sync(0xffffffff, s, o);
    float mean = s * (1.0f / DIMC);

    float q = 0.f;
    #pragma unroll
    for (int i = 0; i < 12; i++) { float d = v[i] - mean; q += d * d; }
    #pragma unroll
    for (int o = 16; o > 0; o >>= 1) q += __shfl_xor_sync(0xffffffff, q, o);
    float r = rsqrtf(q * (1.0f / DIMC) + LN_EPS);

    float* orow = out + (size_t)row * DIMC;
    #pragma unroll
    for (int i = 0; i < 12; i++) {
        int c = lane + 32 * i;
        orow[perm8(c)] = tf32r((v[i] - mean) * r * w[c] + b[c]);
    }
}

// ============================================================
// TF32 TC GEMM: C[M,N] = A[M,K] @ W[N,K]^T (+epilogue)
// A/W pre-rounded and pair-permuted -> raw cp.async, v2 frag loads.
// MT x 128 tile, BK=16, 4-stage pipeline (wait_group 2), 256 thr.
// EPI 0: qkv out (Q/K perm8; V section transposed into vt)
// EPI 1: +bias +res, fp32 natural
// EPI 2: +bias, exact GELU, tf32-rounded, perm8
// ============================================================
#define PST 20
#define GEMM_SMEM(MT) (4 * ((MT) + 128) * PST * 4)

template <int EPI, int MT>
__global__ __launch_bounds__(256, 2)
void gemm_tc(const float* __restrict__ A, const float* __restrict__ W,
             const float* __restrict__ bias, const float* __restrict__ res,
             float* __restrict__ C, float* __restrict__ vt, int M, int N, int K) {
    extern __shared__ float smem[];
    const int ASLOT = MT * PST;
    const int BSLOT = 128 * PST;
    float* As = smem;                    // [4][ASLOT]
    float* Bs = smem + 4 * ASLOT;        // [4][BSLOT]
    uint32_t As_u = (uint32_t)__cvta_generic_to_shared(As);
    uint32_t Bs_u = (uint32_t)__cvta_generic_to_shared(Bs);

    int tid = threadIdx.x;
    int lane = tid & 31, wid = tid >> 5;
    int wm = wid >> 2, wn = wid & 3;
    int j = lane & 3, lr4 = lane >> 2;
    int m0 = blockIdx.y * MT, n0 = blockIdx.x * 128;

    // A loader: 16 floats per row per stage; MT=128 -> 2 thr/row covers 256? 
    // BK=16: one row = 16 floats = 4 cp.async chunks; MT=128 -> 2 rows/thr? 
    // use: 256 thr, each loads 16B; A needs MT*16/4 = MT*4 chunks.
    // MT=128: 512 chunks A -> 2 per thread; B: 512 chunks -> 2 per thread.
    // MT=64: 256 chunks A -> 1 per thread.
    const int ACH = MT * 4 / 256;              // chunks per thread for A (2 or 1)
    int arow = tid / (256 / (MT / 4 * 4 / 4)); // unused; compute directly below
    (void)arow;
    // A: chunk id = tid (+256): row = ch/4, off = (ch%4)*4
    // B: same with 128 rows -> 512 chunks: ch = tid, tid+256

    const int MI = MT / 32;
    float acc[MI][4][4];
    #pragma unroll
    for (int mi = 0; mi < MI; mi++)
        #pragma unroll
        for (int ni = 0; ni < 4; ni++)
            #pragma unroll
            for (int r = 0; r < 4; r++) acc[mi][ni][r] = 0.f;

    int T = K / 16;

    // prologue: stages 0..2
    #pragma unroll
    for (int t = 0; t < 3; t++) {
        #pragma unroll
        for (int cch = 0; cch < ACH; cch++) {
            int ch = tid + cch * 256;
            int row_ = ch >> 2, off = (ch & 3) * 4;
            cpa16(As_u + (t * ASLOT + row_ * PST + off) * 4,
                  A + (size_t)(m0 + row_) * K + t * 16 + off);
        }
        #pragma unroll
        for (int cch = 0; cch < 2; cch++) {
            int ch = tid + cch * 256;
            int row_ = ch >> 2, off = (ch & 3) * 4;
            cpa16(Bs_u + (t * BSLOT + row_ * PST + off) * 4,
                  W + (size_t)(n0 + row_) * K + t * 16 + off);
        }
        asm volatile("cp.async.commit_group;");
    }

    for (int t = 0; t < T; t++) {
        if (t + 3 <= T) asm volatile("cp.async.wait_group 2;");
        else if (t + 2 <= T) asm volatile("cp.async.wait_group 1;");
        else asm volatile("cp.async.wait_group 0;");
        __syncthreads();
        if (t + 3 < T) {
            int sl = (t + 3) & 3;
            #pragma unroll
            for (int cch = 0; cch < ACH; cch++) {
                int ch = tid + cch * 256;
                int row_ = ch >> 2, off = (ch & 3) * 4;
                cpa16(As_u + (sl * ASLOT + row_ * PST + off) * 4,
                      A + (size_t)(m0 + row_) * K + (t + 3) * 16 + off);
            }
            #pragma unroll
            for (int cch = 0; cch < 2; cch++) {
                int ch = tid + cch * 256;
                int row_ = ch >> 2, off = (ch & 3) * 4;
                cpa16(Bs_u + (sl * BSLOT + row_ * PST + off) * 4,
                      W + (size_t)(n0 + row_) * K + (t + 3) * 16 + off);
            }
            asm volatile("cp.async.commit_group;");
        }
        const float* Ast = As + (t & 3) * ASLOT;
        const float* Bst = Bs + (t & 3) * BSLOT;
        #pragma unroll
        for (int kk = 0; kk < 16; kk += 8) {
            float2 af0[MI], af1[MI];
            #pragma unroll
            for (int mi = 0; mi < MI; mi++) {
                int mr = wm * (MT / 2) + mi * 16 + lr4;
                af0[mi] = *(const float2*)&Ast[mr * PST + kk + 2 * j];
                af1[mi] = *(const float2*)&Ast[(mr + 8) * PST + kk + 2 * j];
            }
            #pragma unroll
            for (int ni = 0; ni < 4; ni++) {
                int nr = wn * 32 + ni * 8 + lr4;
                float2 bf = *(const float2*)&Bst[nr * PST + kk + 2 * j];
                #pragma unroll
                for (int mi = 0; mi < MI; mi++)
                    mma_tf32f(acc[mi][ni], af0[mi].x, af1[mi].x,
                              af0[mi].y, af1[mi].y, bf.x, bf.y);
            }
        }
    }

    #pragma unroll
    for (int mi = 0; mi < MI; mi++) {
        int r = m0 + wm * (MT / 2) + mi * 16 + lr4;
        #pragma unroll
        for (int ni = 0; ni < 4; ni++) {
            int c = n0 + wn * 32 + ni * 8 + 2 * j;
            float v[4] = {acc[mi][ni][0], acc[mi][ni][1], acc[mi][ni][2], acc[mi][ni][3]};
            int rr[2] = {r, r + 8};
            #pragma unroll
            for (int half = 0; half < 2; half++) {
                float x0 = v[half * 2 + 0], x1 = v[half * 2 + 1];
                float* cr = C + (size_t)rr[half] * N;
                if (EPI == 0) {
                    if (c < 768) {
                        // Q/K sections: pair-permuted in place
                        cr[perm8(c)]     = tf32r(x0);
                        cr[perm8(c + 1)] = tf32r(x1);
                    } else {
                        // V section: write transposed into vt[bh][d][seq],
                        // seq pair-permuted (matches F pad permutation)
                        int b_ = rr[half] >> 10;          // row / SEQ
                        int n_ = rr[half] & (SEQ - 1);
                        int np = perm8(n_);
                        int hd0 = c - 768;                // h*64 + d
                        float* vtb = vt + ((size_t)b_ * NH * HD + hd0) * SEQ;
                        vtb[np]       = tf32r(x0);
                        vtb[SEQ + np] = tf32r(x1);        // d+1 row
                    }
                }
                if (EPI == 1) {
                    const float* rrow = res + (size_t)rr[half] * N;
                    x0 += bias[c] + rrow[c];
                    x1 += bias[c + 1] + rrow[c + 1];
                    *(float2*)(cr + c) = make_float2(x0, x1);
                }
                if (EPI == 2) {
                    x0 += bias[c];
                    x1 += bias[c + 1];
                    cr[perm8(c)]     = tf32r(0.5f * x0 * (1.0f + erff(x0 * 0.70710678118654752f)));
                    cr[perm8(c + 1)] = tf32r(0.5f * x1 * (1.0f + erff(x1 * 0.70710678118654752f)));
                }
            }
        }
    }
}

// ============================================================
// L2Q attention: 256 thr / 8 warps, Q tile 128 rows, K tile 64.
// Q/K pair-permuted in qkv; V pre-transposed in g_vt (seq permuted).
// All fragment loads are v2. Double-buffered cp.async.
// ============================================================
#define AKS 72
#define KV_TILE (64*AKS)
#define FPAD (16*AKS)
#define ATTN_SMEM ((4*KV_TILE + 8*FPAD) * 4)   // 110592 B

__global__ __launch_bounds__(256, 2)
void attn_tc(const float* __restrict__ qkv, const float* __restrict__ vt,
             const float* __restrict__ alpha, const float* __restrict__ beta,
             const float* __restrict__ gamma, float* __restrict__ ao) {
    extern __shared__ float sm[];
    float* Ks = sm;
    float* Vs = sm + 2 * KV_TILE;          // holds Vt tiles [d][key]
    float* Fw = sm + 4 * KV_TILE;
    uint32_t Ks_u = (uint32_t)__cvta_generic_to_shared(Ks);
    uint32_t Vs_u = (uint32_t)__cvta_generic_to_shared(Vs);

    int tid = threadIdx.x, lane = tid & 31, wid = tid >> 5;
    int j = lane & 3, lr4 = lane >> 2;
    int bh = blockIdx.y;
    int b = bh / NH, h = bh % NH;
    int r0 = blockIdx.x * 128;
    float al = alpha[h], be = beta[h], ga = gamma[h];

    const float* qbase = qkv + (size_t)b * SEQ * (3 * DIMC) + h * HD;
    const float* kbase = qbase + DIMC;
    const float* vtb = vt + (size_t)bh * HD * SEQ;

    int row0 = wid * 16 + lr4;
    float* fw = Fw + wid * FPAD;

    // Q fragments (pair-permuted in gmem -> float2 loads)
    float qf[8][4];
    {
        const float* qlo = qbase + (size_t)(r0 + row0) * (3 * DIMC);
        const float* qhi = qlo + 8 * (3 * DIMC);
        #pragma unroll
        for (int dk = 0; dk < 8; dk++) {
            float2 q0 = *(const float2*)(qlo + dk * 8 + 2 * j);
            float2 q1 = *(const float2*)(qhi + dk * 8 + 2 * j);
            qf[dk][0] = q0.x;
            qf[dk][1] = q1.x;
            qf[dk][2] = q0.y;
            qf[dk][3] = q1.y;
        }
    }

    float oacc[8][4];
    #pragma unroll
    for (int i = 0; i < 8; i++)
        #pragma unroll
        for (int r = 0; r < 4; r++) oacc[i][r] = 0.f;
    float den0 = 0.f, den1 = 0.f;

    int lrow = tid >> 2;            // K: key row / Vt: d row
    int lq = (tid & 3) * 16;
    uint32_t s_off = (lrow * AKS + lq) * 4;

    {
        const float* kr = kbase + (size_t)lrow * (3 * DIMC) + lq;
        const float* vr = vtb + (size_t)lrow * SEQ + lq;
        #pragma unroll
        for (int i = 0; i < 4; i++) {
            cpa16(Ks_u + s_off + i * 16, kr + i * 4);
            cpa16(Vs_u + s_off + i * 16, vr + i * 4);
        }
        asm volatile("cp.async.commit_group;");
    }

    const int NT = SEQ / 64;
    for (int t = 0; t < NT; t++) {
        int s = t & 1;
        asm volatile("cp.async.wait_group 0;");
        __syncthreads();
        if (t + 1 < NT) {
            int s2 = s ^ 1;
            const float* kr = kbase + (size_t)((t + 1) * 64 + lrow) * (3 * DIMC) + lq;
            const float* vr = vtb + (size_t)lrow * SEQ + (t + 1) * 64 + lq;
            uint32_t kb = Ks_u + s2 * KV_TILE * 4 + s_off;
            uint32_t vb = Vs_u + s2 * KV_TILE * 4 + s_off;
            #pragma unroll
            for (int i = 0; i < 4; i++) {
                cpa16(kb + i * 16, kr + i * 4);
                cpa16(vb + i * 16, vr + i * 4);
            }
            asm volatile("cp.async.commit_group;");
        }
        const float* Kt = Ks + s * KV_TILE;
        const float* Vt = Vs + s * KV_TILE;

        // S = Q K^T
        float sacc[8][4];
        #pragma unroll
        for (int i = 0; i < 8; i++)
            #pragma unroll
            for (int r = 0; r < 4; r++) sacc[i][r] = 0.f;

        #pragma unroll
        for (int kk = 0; kk < 64; kk += 8) {
            int dk = kk >> 3;
            #pragma unroll
            for (int ni = 0; ni < 8; ni++) {
                int br = ni * 8 + lr4;
                float2 bf = *(const float2*)&Kt[br * AKS + kk + 2 * j];
                mma_tf32f(sacc[ni], qf[dk][0], qf[dk][1], qf[dk][2], qf[dk][3],
                          bf.x, bf.y);
            }
        }

        // transform; write F pair-permuted (over key) into warp pad
        #pragma unroll
        for (int ni = 0; ni < 8; ni++) {
            int c0 = ni * 8 + 2 * j;
            float s0 = sacc[ni][0] * 0.125f;
            float s1 = sacc[ni][1] * 0.125f;
            float s2 = sacc[ni][2] * 0.125f;
            float s3 = sacc[ni][3] * 0.125f;
            float f0 = fmaxf(fmaf(al * s0, s0, fmaf(be, s0, ga)), 0.f);
            float f1 = fmaxf(fmaf(al * s1, s1, fmaf(be, s1, ga)), 0.f);
            float f2 = fmaxf(fmaf(al * s2, s2, fmaf(be, s2, ga)), 0.f);
            float f3 = fmaxf(fmaf(al * s3, s3, fmaf(be, s3, ga)), 0.f);
            den0 += f0 + f1;
            den1 += f2 + f3;
            int p0 = perm8(c0), p1 = perm8(c0 + 1);
            fw[lr4 * AKS + p0]       = tf32r(f0);
            fw[lr4 * AKS + p1]       = tf32r(f1);
            fw[(lr4 + 8) * AKS + p0] = tf32r(f2);
            fw[(lr4 + 8) * AKS + p1] = tf32r(f3);
        }
        __syncwarp();

        // O += F V : B-frag from Vt[d][key] -> v2 over permuted key
        #pragma unroll
        for (int kk = 0; kk < 64; kk += 8) {
            float2 falo = *(const float2*)&fw[lr4 * AKS + kk + 2 * j];
            float2 fahi = *(const float2*)&fw[(lr4 + 8) * AKS + kk + 2 * j];
            #pragma unroll
            for (int ni = 0; ni < 8; ni++) {
                int nd = ni * 8 + lr4;      // d index
                float2 bf = *(const float2*)&Vt[nd * AKS + kk + 2 * j];
                mma_tf32f(oacc[ni], falo.x, fahi.x, falo.y, fahi.y, bf.x, bf.y);
            }
        }
        __syncwarp();
    }

    den0 += __shfl_xor_sync(0xffffffff, den0, 1);
    den0 += __shfl_xor_sync(0xffffffff, den0, 2);
    den1 += __shfl_xor_sync(0xffffffff, den1, 1);
    den1 += __shfl_xor_sync(0xffffffff, den1, 2);
    float di0 = 1.0f / (den0 + 1e-6f);
    float di1 = 1.0f / (den1 + 1e-6f);

    // output pair-permuted (feeds proj's A operand)
    float* olo = ao + (size_t)(b * SEQ + r0 + row0) * DIMC + h * HD;
    float* ohi = olo + 8 * DIMC;
    #pragma unroll
    for (int ni = 0; ni < 8; ni++) {
        int c0 = ni * 8 + 2 * j;
        int p0 = perm8(c0), p1 = perm8(c0 + 1);
        olo[p0] = tf32r(oacc[ni][0] * di0);
        olo[p1] = tf32r(oacc[ni][1] * di0);
        ohi[p0] = tf32r(oacc[ni][2] * di1);
        ohi[p1] = tf32r(oacc[ni][3] * di1);
    }
}

// ============================================================
// launch
// ============================================================
extern "C" void kernel_launch(void* const* d_in, const int* in_sizes, int n_in,
                              void* d_out, int out_size) {
    const float* x      = (const float*)d_in[0];
    const float* qkv_w  = (const float*)d_in[1];
    const float* proj_w = (const float*)d_in[2];
    const float* proj_b = (const float*)d_in[3];
    const float* alpha  = (const float*)d_in[4];
    const float* beta   = (const float*)d_in[5];
    const float* gamma  = (const float*)d_in[6];
    const float* ln1_w  = (const float*)d_in[7];
    const float* ln1_b  = (const float*)d_in[8];
    const float* ln2_w  = (const float*)d_in[9];
    const float* ln2_b  = (const float*)d_in[10];
    const float* w1     = (const float*)d_in[11];
    const float* b1     = (const float*)d_in[12];
    const float* w2     = (const float*)d_in[13];
    const float* b2     = (const float*)d_in[14];
    float* out = (float*)d_out;

    float *h, *qkv, *vt, *ao, *x1, *m, *wq, *wp, *ww1, *ww2;
    cudaGetSymbolAddress((void**)&h,   g_h);
    cudaGetSymbolAddress((void**)&qkv, g_qkv);
    cudaGetSymbolAddress((void**)&vt,  g_vt);
    cudaGetSymbolAddress((void**)&ao,  g_ao);
    cudaGetSymbolAddress((void**)&x1,  g_x1);
    cudaGetSymbolAddress((void**)&m,   g_m);
    cudaGetSymbolAddress((void**)&wq,  g_wq);
    cudaGetSymbolAddress((void**)&wp,  g_wp);
    cudaGetSymbolAddress((void**)&ww1, g_w1);
    cudaGetSymbolAddress((void**)&ww2, g_w2);

    cudaFuncSetAttribute((const void*)gemm_tc<0,128>, cudaFuncAttributeMaxDynamicSharedMemorySize, GEMM_SMEM(128));
    cudaFuncSetAttribute((const void*)gemm_tc<2,128>, cudaFuncAttributeMaxDynamicSharedMemorySize, GEMM_SMEM(128));
    cudaFuncSetAttribute((const void*)gemm_tc<1,64>,  cudaFuncAttributeMaxDynamicSharedMemorySize, GEMM_SMEM(64));
    cudaFuncSetAttribute((const void*)attn_tc,        cudaFuncAttributeMaxDynamicSharedMemorySize, ATTN_SMEM);

    round_w<<<(NW_1 + 255) / 256, 256>>>(qkv_w, wq, proj_w, wp, w1, ww1, w2, ww2);
    ln_kernel<<<M_TOT / 8, 256>>>(x, ln1_w, ln1_b, h);
    gemm_tc<0,128><<<dim3(3 * DIMC / 128, M_TOT / 128), 256, GEMM_SMEM(128)>>>(
        h, wq, nullptr, nullptr, qkv, vt, M_TOT, 3 * DIMC, DIMC);
    attn_tc<<<dim3(SEQ / 128, BATCH * NH), 256, ATTN_SMEM>>>(qkv, vt, alpha, beta, gamma, ao);
    gemm_tc<1,64><<<dim3(DIMC / 128, M_TOT / 64), 256, GEMM_SMEM(64)>>>(
        ao, wp, proj_b, x, x1, nullptr, M_TOT, DIMC, DIMC);
    ln_kernel<<<M_TOT / 8, 256>>>(x1, ln2_w, ln2_b, h);
    gemm_tc<2,128><<<dim3(MLPD / 128, M_TOT / 128), 256, GEMM_SMEM(128)>>>(
        h, ww1, b1, nullptr, m, nullptr, M_TOT, MLPD, DIMC);
    gemm_tc<1,64><<<dim3(DIMC / 128, M_TOT / 64), 256, GEMM_SMEM(64)>>>(
        m, ww2, b2, x1, out, nullptr, M_TOT, DIMC, MLPD);
}

// round 9
// speedup vs baseline: 4.0468x; 2.1732x over previous
#include <cuda_runtime.h>
#include <cuda_fp16.h>
#include <math.h>
#include <stdint.h>

#define DIMC 384
#define NH 6
#define HD 64
#define MLPD 1536
#define BATCH 8
#define SEQ 1024
#define M_TOT (BATCH*SEQ)
#define LN_EPS 1e-5f

#define NW_QKV (3*DIMC*DIMC)
#define NW_PROJ (DIMC*DIMC)
#define NW_1 (MLPD*DIMC)
#define NW_2 (DIMC*MLPD)

__device__ __half g_h[M_TOT * DIMC];
__device__ __half g_qkv[M_TOT * 3 * DIMC];
__device__ __half g_vt[BATCH * NH * HD * SEQ];
__device__ __half g_ao[M_TOT * DIMC];
__device__ float  g_x1[M_TOT * DIMC];
__device__ __half g_m[M_TOT * MLPD];
__device__ __half g_wq[NW_QKV];
__device__ __half g_wp[NW_PROJ];
__device__ __half g_w1[NW_1];
__device__ __half g_w2[NW_2];

// fp16 pair permutation within 16-element k-groups: pair p -> slot (p%4)*2 + p/4,
// so an 8-byte load at half-offset 4j yields pairs (j, j+4) = k{2j,2j+1},{2j+8,2j+9}
// = exactly one m16n8k16 fragment register pair.
__device__ __forceinline__ int perm16h(int c) {
    int p = (c >> 1) & 7;
    int s = ((p & 3) << 1) | (p >> 2);
    return (c & ~15) | (s << 1) | (c & 1);
}
// pair-slot destination for a consecutive (c0, c0+1) pair, c0 even
__device__ __forceinline__ int pairdst(int c0) {
    int p = (c0 >> 1) & 7;
    int s = ((p & 3) << 1) | (p >> 2);
    return (c0 & ~15) | (s << 1);
}

__device__ __forceinline__ void mma_f16(float c[4], uint32_t a0, uint32_t a1,
                                        uint32_t a2, uint32_t a3,
                                        uint32_t b0, uint32_t b1) {
    asm volatile(
        "mma.sync.aligned.m16n8k16.row.col.f32.f16.f16.f32 "
        "{%0,%1,%2,%3},{%4,%5,%6,%7},{%8,%9},{%0,%1,%2,%3};\n"
        : "+f"(c[0]), "+f"(c[1]), "+f"(c[2]), "+f"(c[3])
        : "r"(a0), "r"(a1), "r"(a2), "r"(a3), "r"(b0), "r"(b1));
}

__device__ __forceinline__ void cpa16(uint32_t s, const void* g) {
    asm volatile("cp.async.cg.shared.global [%0], [%1], 16;" :: "r"(s), "l"(g));
}

// ============================================================
// one-shot weight rounding to fp16 + pair permutation along K
// ============================================================
__global__ __launch_bounds__(256)
void round_w(const float* __restrict__ a, __half* __restrict__ oa,
             const float* __restrict__ b, __half* __restrict__ ob,
             const float* __restrict__ c, __half* __restrict__ oc,
             const float* __restrict__ d, __half* __restrict__ od) {
    int i = blockIdx.x * 256 + threadIdx.x;
    int p = perm16h(i);
    if (i < NW_QKV)  oa[p] = __float2half_rn(a[i]);
    if (i < NW_PROJ) ob[p] = __float2half_rn(b[i]);
    if (i < NW_1) { oc[p] = __float2half_rn(c[i]); od[p] = __float2half_rn(d[i]); }
}

// ============================================================
// LayerNorm: one warp per row; fp16 pair-permuted output
// ============================================================
__global__ __launch_bounds__(256)
void ln_kernel(const float* __restrict__ x, const float* __restrict__ w,
               const float* __restrict__ b, __half* __restrict__ out) {
    int lane = threadIdx.x & 31;
    int row = blockIdx.x * 8 + (threadIdx.x >> 5);
    const float* xr = x + (size_t)row * DIMC;

    float v[12];
    float s = 0.f;
    #pragma unroll
    for (int i = 0; i < 12; i++) { v[i] = xr[lane + 32 * i]; s += v[i]; }
    #pragma unroll
    for (int o = 16; o > 0; o >>= 1) s += __shfl_xor_sync(0xffffffff, s, o);
    float mean = s * (1.0f / DIMC);

    float q = 0.f;
    #pragma unroll
    for (int i = 0; i < 12; i++) { float d = v[i] - mean; q += d * d; }
    #pragma unroll
    for (int o = 16; o > 0; o >>= 1) q += __shfl_xor_sync(0xffffffff, q, o);
    float r = rsqrtf(q * (1.0f / DIMC) + LN_EPS);

    __half* orow = out + (size_t)row * DIMC;
    #pragma unroll
    for (int i = 0; i < 12; i++) {
        int c = lane + 32 * i;
        orow[perm16h(c)] = __float2half_rn((v[i] - mean) * r * w[c] + b[c]);
    }
}

// ============================================================
// FP16 TC GEMM: C[M,N] = A[M,K] @ W[N,K]^T (+epilogue)
// A/W fp16, pair-permuted -> all fragment loads are LDS.64.
// MT x 128 tile, BK=32, 4-stage cp.async, 256 thr, warps 2x4.
// smem stride 48 halfs (96 B/row): conflict-free 8B phases.
// EPI 0: qkv out (Q/K perm16h half2; V transposed+permuted to vt)
// EPI 1: +bias +res, fp32 natural out
// EPI 2: +bias, exact GELU, fp16 perm16h out
// ============================================================
#define SH 48
#define GEMM_SMEM(MT) (4 * ((MT) + 128) * SH * 2)

template <int EPI, int MT>
__global__ __launch_bounds__(256, 2)
void gemm_tc(const __half* __restrict__ A, const __half* __restrict__ W,
             const float* __restrict__ bias, const float* __restrict__ res,
             float* __restrict__ Cf, __half* __restrict__ Ch,
             __half* __restrict__ vt, int M, int N, int K) {
    extern __shared__ __half smemh[];
    const int ASLOT = MT * SH;
    const int BSLOT = 128 * SH;
    __half* As = smemh;                  // [4][ASLOT]
    __half* Bs = smemh + 4 * ASLOT;      // [4][BSLOT]
    uint32_t As_u = (uint32_t)__cvta_generic_to_shared(As);
    uint32_t Bs_u = (uint32_t)__cvta_generic_to_shared(Bs);

    int tid = threadIdx.x;
    int lane = tid & 31, wid = tid >> 5;
    int wm = wid >> 2, wn = wid & 3;
    int j = lane & 3, lr4 = lane >> 2;
    int m0 = blockIdx.y * MT, n0 = blockIdx.x * 128;

    const int ACH = MT / 64;             // A 16B-chunks per thread (2 or 1)
    const int MI = MT / 32;
    float acc[MI][4][4];
    #pragma unroll
    for (int mi = 0; mi < MI; mi++)
        #pragma unroll
        for (int ni = 0; ni < 4; ni++)
            #pragma unroll
            for (int r = 0; r < 4; r++) acc[mi][ni][r] = 0.f;

    int T = K / 32;

    // prologue: stages 0..2
    #pragma unroll
    for (int t = 0; t < 3; t++) {
        #pragma unroll
        for (int cch = 0; cch < ACH; cch++) {
            int ch = tid + cch * 256;
            int row_ = ch >> 2, off = (ch & 3) * 8;       // halfs
            cpa16(As_u + (t * ASLOT + row_ * SH + off) * 2,
                  A + (size_t)(m0 + row_) * K + t * 32 + off);
        }
        #pragma unroll
        for (int cch = 0; cch < 2; cch++) {
            int ch = tid + cch * 256;
            int row_ = ch >> 2, off = (ch & 3) * 8;
            cpa16(Bs_u + (t * BSLOT + row_ * SH + off) * 2,
                  W + (size_t)(n0 + row_) * K + t * 32 + off);
        }
        asm volatile("cp.async.commit_group;");
    }

    for (int t = 0; t < T; t++) {
        if (t + 3 <= T) asm volatile("cp.async.wait_group 2;");
        else if (t + 2 <= T) asm volatile("cp.async.wait_group 1;");
        else asm volatile("cp.async.wait_group 0;");
        __syncthreads();
        if (t + 3 < T) {
            int sl = (t + 3) & 3;
            #pragma unroll
            for (int cch = 0; cch < ACH; cch++) {
                int ch = tid + cch * 256;
                int row_ = ch >> 2, off = (ch & 3) * 8;
                cpa16(As_u + (sl * ASLOT + row_ * SH + off) * 2,
                      A + (size_t)(m0 + row_) * K + (t + 3) * 32 + off);
            }
            #pragma unroll
            for (int cch = 0; cch < 2; cch++) {
                int ch = tid + cch * 256;
                int row_ = ch >> 2, off = (ch & 3) * 8;
                cpa16(Bs_u + (sl * BSLOT + row_ * SH + off) * 2,
                      W + (size_t)(n0 + row_) * K + (t + 3) * 32 + off);
            }
            asm volatile("cp.async.commit_group;");
        }
        const __half* Ast = As + (t & 3) * ASLOT;
        const __half* Bst = Bs + (t & 3) * BSLOT;
        #pragma unroll
        for (int kk = 0; kk < 32; kk += 16) {
            uint2 afA[MI], afB[MI];
            #pragma unroll
            for (int mi = 0; mi < MI; mi++) {
                int mr = wm * (MT / 2) + mi * 16 + lr4;
                afA[mi] = *(const uint2*)&Ast[mr * SH + kk + 4 * j];        // (a0,a2)
                afB[mi] = *(const uint2*)&Ast[(mr + 8) * SH + kk + 4 * j];  // (a1,a3)
            }
            #pragma unroll
            for (int ni = 0; ni < 4; ni++) {
                int nr = wn * 32 + ni * 8 + lr4;
                uint2 bf = *(const uint2*)&Bst[nr * SH + kk + 4 * j];       // (b0,b1)
                #pragma unroll
                for (int mi = 0; mi < MI; mi++)
                    mma_f16(acc[mi][ni], afA[mi].x, afB[mi].x,
                            afA[mi].y, afB[mi].y, bf.x, bf.y);
            }
        }
    }

    #pragma unroll
    for (int mi = 0; mi < MI; mi++) {
        int r = m0 + wm * (MT / 2) + mi * 16 + lr4;
        #pragma unroll
        for (int ni = 0; ni < 4; ni++) {
            int c = n0 + wn * 32 + ni * 8 + 2 * j;
            float v[4] = {acc[mi][ni][0], acc[mi][ni][1], acc[mi][ni][2], acc[mi][ni][3]};
            int rr[2] = {r, r + 8};
            #pragma unroll
            for (int half_ = 0; half_ < 2; half_++) {
                float x0 = v[half_ * 2 + 0], x1 = v[half_ * 2 + 1];
                if (EPI == 0) {
                    if (c < 768) {
                        int dst = pairdst(c);
                        *(__half2*)(Ch + (size_t)rr[half_] * N + dst) =
                            __floats2half2_rn(x0, x1);
                    } else {
                        int b_ = rr[half_] >> 10;
                        int n_ = rr[half_] & (SEQ - 1);
                        int np = perm16h(n_);
                        int d0 = c - 768;
                        __half* vtb = vt + ((size_t)b_ * NH * HD + d0) * SEQ;
                        vtb[np]       = __float2half_rn(x0);
                        vtb[SEQ + np] = __float2half_rn(x1);
                    }
                }
                if (EPI == 1) {
                    const float* rrow = res + (size_t)rr[half_] * N;
                    x0 += bias[c] + rrow[c];
                    x1 += bias[c + 1] + rrow[c + 1];
                    *(float2*)(Cf + (size_t)rr[half_] * N + c) = make_float2(x0, x1);
                }
                if (EPI == 2) {
                    x0 += bias[c];
                    x1 += bias[c + 1];
                    x0 = 0.5f * x0 * (1.0f + erff(x0 * 0.70710678118654752f));
                    x1 = 0.5f * x1 * (1.0f + erff(x1 * 0.70710678118654752f));
                    int dst = pairdst(c);
                    *(__half2*)(Ch + (size_t)rr[half_] * N + dst) =
                        __floats2half2_rn(x0, x1);
                }
            }
        }
    }
}

// ============================================================
// L2Q attention, fp16 mma: 256 thr / 8 warps, Q tile 128, K tile 64.
// Q/K pair-permuted in qkv; Vt[d][seq] pair-permuted over seq.
// S-phase per-ni (4-reg sacc). All frag loads LDS.64 (stride 80).
// ============================================================
#define AKH 80
#define KV_TILE (64*AKH)
#define FPAD (16*AKH)
#define ATTN_SMEM ((4*KV_TILE + 8*FPAD) * 2)   // 61440 B

__global__ __launch_bounds__(256, 3)
void attn_tc(const __half* __restrict__ qkv, const __half* __restrict__ vt,
             const float* __restrict__ alpha, const float* __restrict__ beta,
             const float* __restrict__ gamma, __half* __restrict__ ao) {
    extern __shared__ __half smh[];
    __half* Ks = smh;
    __half* Vs = smh + 2 * KV_TILE;
    __half* Fw = smh + 4 * KV_TILE;
    uint32_t Ks_u = (uint32_t)__cvta_generic_to_shared(Ks);
    uint32_t Vs_u = (uint32_t)__cvta_generic_to_shared(Vs);

    int tid = threadIdx.x, lane = tid & 31, wid = tid >> 5;
    int j = lane & 3, lr4 = lane >> 2;
    int bh = blockIdx.y;
    int b = bh / NH, h = bh % NH;
    int r0 = blockIdx.x * 128;
    float al = alpha[h], be = beta[h], ga = gamma[h];

    const __half* qbase = qkv + (size_t)b * SEQ * (3 * DIMC) + h * HD;
    const __half* kbase = qbase + DIMC;
    const __half* vtb = vt + (size_t)bh * HD * SEQ;

    int row0 = wid * 16 + lr4;
    __half* fw = Fw + wid * FPAD;

    // Q fragments: 4 k-steps of 16 d
    uint32_t qf[4][4];
    {
        const __half* qlo = qbase + (size_t)(r0 + row0) * (3 * DIMC);
        const __half* qhi = qlo + 8 * (3 * DIMC);
        #pragma unroll
        for (int dk = 0; dk < 4; dk++) {
            uint2 q0 = *(const uint2*)(qlo + dk * 16 + 4 * j);
            uint2 q1 = *(const uint2*)(qhi + dk * 16 + 4 * j);
            qf[dk][0] = q0.x; qf[dk][1] = q1.x;
            qf[dk][2] = q0.y; qf[dk][3] = q1.y;
        }
    }

    float oacc[8][4];
    #pragma unroll
    for (int i = 0; i < 8; i++)
        #pragma unroll
        for (int r = 0; r < 4; r++) oacc[i][r] = 0.f;
    float den0 = 0.f, den1 = 0.f;

    int lrow = tid >> 2;
    int lq = (tid & 3) * 16;        // halfs
    uint32_t s_off = (lrow * AKH + lq) * 2;

    {
        const __half* kr = kbase + (size_t)lrow * (3 * DIMC) + lq;
        const __half* vr = vtb + (size_t)lrow * SEQ + lq;
        cpa16(Ks_u + s_off,      kr);
        cpa16(Ks_u + s_off + 16, kr + 8);
        cpa16(Vs_u + s_off,      vr);
        cpa16(Vs_u + s_off + 16, vr + 8);
        asm volatile("cp.async.commit_group;");
    }

    const int NT = SEQ / 64;
    for (int t = 0; t < NT; t++) {
        int s = t & 1;
        asm volatile("cp.async.wait_group 0;");
        __syncthreads();
        if (t + 1 < NT) {
            int s2 = s ^ 1;
            const __half* kr = kbase + (size_t)((t + 1) * 64 + lrow) * (3 * DIMC) + lq;
            const __half* vr = vtb + (size_t)lrow * SEQ + (t + 1) * 64 + lq;
            uint32_t kb = Ks_u + s2 * KV_TILE * 2 + s_off;
            uint32_t vb = Vs_u + s2 * KV_TILE * 2 + s_off;
            cpa16(kb, kr);      cpa16(kb + 16, kr + 8);
            cpa16(vb, vr);      cpa16(vb + 16, vr + 8);
            asm volatile("cp.async.commit_group;");
        }
        const __half* Kt = Ks + s * KV_TILE;
        const __half* Vt = Vs + s * KV_TILE;

        // per-ni: S chunk -> transform -> F write (keeps sacc at 4 regs)
        #pragma unroll
        for (int ni = 0; ni < 8; ni++) {
            float sa[4] = {0.f, 0.f, 0.f, 0.f};
            int br = ni * 8 + lr4;
            #pragma unroll
            for (int dk = 0; dk < 4; dk++) {
                uint2 bf = *(const uint2*)&Kt[br * AKH + dk * 16 + 4 * j];
                mma_f16(sa, qf[dk][0], qf[dk][1], qf[dk][2], qf[dk][3], bf.x, bf.y);
            }
            float s0 = sa[0] * 0.125f, s1 = sa[1] * 0.125f;
            float s2 = sa[2] * 0.125f, s3 = sa[3] * 0.125f;
            float f0 = fmaxf(fmaf(al * s0, s0, fmaf(be, s0, ga)), 0.f);
            float f1 = fmaxf(fmaf(al * s1, s1, fmaf(be, s1, ga)), 0.f);
            float f2 = fmaxf(fmaf(al * s2, s2, fmaf(be, s2, ga)), 0.f);
            float f3 = fmaxf(fmaf(al * s3, s3, fmaf(be, s3, ga)), 0.f);
            den0 += f0 + f1;
            den1 += f2 + f3;
            int dst = pairdst(ni * 8 + 2 * j);
            *(__half2*)&fw[lr4 * AKH + dst]       = __floats2half2_rn(f0, f1);
            *(__half2*)&fw[(lr4 + 8) * AKH + dst] = __floats2half2_rn(f2, f3);
        }
        __syncwarp();

        // O += F V
        #pragma unroll
        for (int kk = 0; kk < 64; kk += 16) {
            uint2 fa0 = *(const uint2*)&fw[lr4 * AKH + kk + 4 * j];
            uint2 fa1 = *(const uint2*)&fw[(lr4 + 8) * AKH + kk + 4 * j];
            #pragma unroll
            for (int ni = 0; ni < 8; ni++) {
                int nd = ni * 8 + lr4;
                uint2 bf = *(const uint2*)&Vt[nd * AKH + kk + 4 * j];
                mma_f16(oacc[ni], fa0.x, fa1.x, fa0.y, fa1.y, bf.x, bf.y);
            }
        }
        __syncwarp();
    }

    den0 += __shfl_xor_sync(0xffffffff, den0, 1);
    den0 += __shfl_xor_sync(0xffffffff, den0, 2);
    den1 += __shfl_xor_sync(0xffffffff, den1, 1);
    den1 += __shfl_xor_sync(0xffffffff, den1, 2);
    float di0 = 1.0f / (den0 + 1e-6f);
    float di1 = 1.0f / (den1 + 1e-6f);

    __half* olo = ao + (size_t)(b * SEQ + r0 + row0) * DIMC + h * HD;
    __half* ohi = olo + 8 * DIMC;
    #pragma unroll
    for (int ni = 0; ni < 8; ni++) {
        int dst = pairdst(ni * 8 + 2 * j);
        *(__half2*)(olo + dst) = __floats2half2_rn(oacc[ni][0] * di0, oacc[ni][1] * di0);
        *(__half2*)(ohi + dst) = __floats2half2_rn(oacc[ni][2] * di1, oacc[ni][3] * di1);
    }
}

// ============================================================
// launch
// ============================================================
extern "C" void kernel_launch(void* const* d_in, const int* in_sizes, int n_in,
                              void* d_out, int out_size) {
    const float* x      = (const float*)d_in[0];
    const float* qkv_w  = (const float*)d_in[1];
    const float* proj_w = (const float*)d_in[2];
    const float* proj_b = (const float*)d_in[3];
    const float* alpha  = (const float*)d_in[4];
    const float* beta   = (const float*)d_in[5];
    const float* gamma  = (const float*)d_in[6];
    const float* ln1_w  = (const float*)d_in[7];
    const float* ln1_b  = (const float*)d_in[8];
    const float* ln2_w  = (const float*)d_in[9];
    const float* ln2_b  = (const float*)d_in[10];
    const float* w1     = (const float*)d_in[11];
    const float* b1     = (const float*)d_in[12];
    const float* w2     = (const float*)d_in[13];
    const float* b2     = (const float*)d_in[14];
    float* out = (float*)d_out;

    __half *h, *qkv, *vt, *ao, *m, *wq, *wp, *ww1, *ww2;
    float *x1;
    cudaGetSymbolAddress((void**)&h,   g_h);
    cudaGetSymbolAddress((void**)&qkv, g_qkv);
    cudaGetSymbolAddress((void**)&vt,  g_vt);
    cudaGetSymbolAddress((void**)&ao,  g_ao);
    cudaGetSymbolAddress((void**)&x1,  g_x1);
    cudaGetSymbolAddress((void**)&m,   g_m);
    cudaGetSymbolAddress((void**)&wq,  g_wq);
    cudaGetSymbolAddress((void**)&wp,  g_wp);
    cudaGetSymbolAddress((void**)&ww1, g_w1);
    cudaGetSymbolAddress((void**)&ww2, g_w2);

    cudaFuncSetAttribute((const void*)gemm_tc<0,128>, cudaFuncAttributeMaxDynamicSharedMemorySize, GEMM_SMEM(128));
    cudaFuncSetAttribute((const void*)gemm_tc<2,128>, cudaFuncAttributeMaxDynamicSharedMemorySize, GEMM_SMEM(128));
    cudaFuncSetAttribute((const void*)gemm_tc<1,64>,  cudaFuncAttributeMaxDynamicSharedMemorySize, GEMM_SMEM(64));
    cudaFuncSetAttribute((const void*)attn_tc,        cudaFuncAttributeMaxDynamicSharedMemorySize, ATTN_SMEM);

    round_w<<<(NW_1 + 255) / 256, 256>>>(qkv_w, wq, proj_w, wp, w1, ww1, w2, ww2);
    ln_kernel<<<M_TOT / 8, 256>>>(x, ln1_w, ln1_b, h);
    gemm_tc<0,128><<<dim3(3 * DIMC / 128, M_TOT / 128), 256, GEMM_SMEM(128)>>>(
        h, wq, nullptr, nullptr, nullptr, qkv, vt, M_TOT, 3 * DIMC, DIMC);
    attn_tc<<<dim3(SEQ / 128, BATCH * NH), 256, ATTN_SMEM>>>(qkv, vt, alpha, beta, gamma, ao);
    gemm_tc<1,64><<<dim3(DIMC / 128, M_TOT / 64), 256, GEMM_SMEM(64)>>>(
        ao, wp, proj_b, x, x1, nullptr, nullptr, M_TOT, DIMC, DIMC);
    ln_kernel<<<M_TOT / 8, 256>>>(x1, ln2_w, ln2_b, h);
    gemm_tc<2,128><<<dim3(MLPD / 128, M_TOT / 128), 256, GEMM_SMEM(128)>>>(
        h, ww1, b1, nullptr, nullptr, m, nullptr, M_TOT, MLPD, DIMC);
    gemm_tc<1,64><<<dim3(DIMC / 128, M_TOT / 64), 256, GEMM_SMEM(64)>>>(
        m, ww2, b2, x1, out, nullptr, nullptr, M_TOT, DIMC, MLPD);
}